// round 1
// baseline (speedup 1.0000x reference)
#include <cuda_runtime.h>
#include <cuda_bf16.h>
#include <math.h>

// Problem constants
#define BATCH   2
#define SEQ     2048
#define DIN     2048
#define DOUT    2048
#define NHEADS  32
#define NKV     8
#define HD      64
#define NREP    4
#define MROWS   (BATCH * SEQ)      // 4096

// Scratch (allocation-free rule: __device__ globals)
__device__ float g_q[(size_t)BATCH * NHEADS * SEQ * HD];   // [b,h,s,d] 32MB
__device__ float g_k[(size_t)BATCH * NKV * SEQ * HD];      // [b,g,s,d]  8MB
__device__ float g_v[(size_t)BATCH * NKV * SEQ * HD];      //            8MB
__device__ float g_ctx[(size_t)MROWS * DOUT];              // [b*s, h*d] 32MB

// ----------------------------------------------------------------------------
// Tiled fp32 GEMM: C[M=4096, N] = A[4096, 2048] * W[2048, N]
// mode 0: scatter to [b, h, s, d] layout (Hh heads)
// mode 1: row-major out + bias
// ----------------------------------------------------------------------------
__global__ __launch_bounds__(256)
void gemm128_kernel(const float* __restrict__ A, const float* __restrict__ W,
                    float* __restrict__ out, int N, int Hh,
                    const float* __restrict__ bias, int mode)
{
    __shared__ float As[16][128];
    __shared__ float Ws[16][128];

    const int tid = threadIdx.x;
    const int tm = tid >> 4;      // 0..15
    const int tn = tid & 15;      // 0..15
    const int row0 = blockIdx.y * 128;
    const int col0 = blockIdx.x * 128;

    float c[8][8];
#pragma unroll
    for (int i = 0; i < 8; i++)
#pragma unroll
        for (int j = 0; j < 8; j++) c[i][j] = 0.f;

    for (int k0 = 0; k0 < DIN; k0 += 16) {
        // Load A tile 128x16 (512 float4), store transposed As[k][m]
#pragma unroll
        for (int r = 0; r < 2; r++) {
            int idx = tid + r * 256;          // 0..511
            int ar  = idx >> 2;               // 0..127
            int ac4 = idx & 3;                // 0..3
            float4 v = *(const float4*)&A[(size_t)(row0 + ar) * DIN + k0 + ac4 * 4];
            As[ac4 * 4 + 0][ar] = v.x;
            As[ac4 * 4 + 1][ar] = v.y;
            As[ac4 * 4 + 2][ar] = v.z;
            As[ac4 * 4 + 3][ar] = v.w;
        }
        // Load W tile 16x128
#pragma unroll
        for (int r = 0; r < 2; r++) {
            int idx = tid + r * 256;
            int wr  = idx >> 5;               // 0..15
            int wc4 = idx & 31;               // 0..31
            *(float4*)&Ws[wr][wc4 * 4] =
                *(const float4*)&W[(size_t)(k0 + wr) * N + col0 + wc4 * 4];
        }
        __syncthreads();

#pragma unroll
        for (int kk = 0; kk < 16; kk++) {
            float4 a0 = *(const float4*)&As[kk][tm * 4];
            float4 a1 = *(const float4*)&As[kk][tm * 4 + 64];
            float4 b0 = *(const float4*)&Ws[kk][tn * 4];
            float4 b1 = *(const float4*)&Ws[kk][tn * 4 + 64];
            float av[8] = {a0.x, a0.y, a0.z, a0.w, a1.x, a1.y, a1.z, a1.w};
            float bv[8] = {b0.x, b0.y, b0.z, b0.w, b1.x, b1.y, b1.z, b1.w};
#pragma unroll
            for (int i = 0; i < 8; i++)
#pragma unroll
                for (int j = 0; j < 8; j++)
                    c[i][j] += av[i] * bv[j];
        }
        __syncthreads();
    }

    int rr[8], cc[8];
#pragma unroll
    for (int i = 0; i < 4; i++) {
        rr[i]     = row0 + tm * 4 + i;
        rr[i + 4] = row0 + 64 + tm * 4 + i;
        cc[i]     = col0 + tn * 4 + i;
        cc[i + 4] = col0 + 64 + tn * 4 + i;
    }

    if (mode == 0) {
#pragma unroll
        for (int i = 0; i < 8; i++) {
            int m = rr[i];
            int b = m >> 11;          // /2048
            int s = m & 2047;
#pragma unroll
            for (int j = 0; j < 8; j++) {
                int n = cc[j];
                int h = n >> 6;
                int d = n & 63;
                out[(((size_t)(b * Hh + h)) * SEQ + s) * HD + d] = c[i][j];
            }
        }
    } else {
#pragma unroll
        for (int i = 0; i < 8; i++)
#pragma unroll
            for (int j = 0; j < 8; j++)
                out[(size_t)rr[i] * N + cc[j]] = c[i][j] + bias[cc[j]];
    }
}

// ----------------------------------------------------------------------------
// RoPE (in-place on [BH, S, 64])
// out[:32] = t1*cos - t2*sin ; out[32:] = t2*cos + t1*sin  (cos/sin duplicated)
// ----------------------------------------------------------------------------
__global__ void rope_kernel(float* __restrict__ buf,
                            const float* __restrict__ cosT,
                            const float* __restrict__ sinT, int BH)
{
    int idx = blockIdx.x * blockDim.x + threadIdx.x;
    int total = BH * SEQ * 32;
    if (idx >= total) return;
    int d  = idx & 31;
    int s  = (idx >> 5) & (SEQ - 1);
    int bh = idx >> 16;                      // 32 * 2048 = 65536
    float* p = buf + ((size_t)bh * SEQ + s) * HD;
    float t1 = p[d];
    float t2 = p[d + 32];
    float cv = cosT[s * HD + d];
    float sv = sinT[s * HD + d];
    p[d]      = t1 * cv - t2 * sv;
    p[d + 32] = t2 * cv + t1 * sv;
}

// ----------------------------------------------------------------------------
// Flash attention (fp32), 64x64 tiles. Grid: (S/64, B*NHEADS).
// Writes ctx in [b*s, h*64+d] row-major so the out-proj GEMM reads it directly.
// ----------------------------------------------------------------------------
__global__ __launch_bounds__(256)
void attn_kernel(const float* __restrict__ q, const float* __restrict__ k,
                 const float* __restrict__ v, float* __restrict__ ctx)
{
    __shared__ float Qs[64][64];    // [row][d]
    __shared__ float KVs[64][64];   // K phase: [d][col] (transposed); V phase: [row][d]
    __shared__ float Ps[64][64];    // probabilities

    const int tid = threadIdx.x;
    const int tm = tid >> 4;   // 0..15 -> rows tm*4..tm*4+3
    const int tn = tid & 15;   // 0..15 -> cols tn*4..tn*4+3

    const int bh = blockIdx.y;
    const int b  = bh >> 5;
    const int h  = bh & 31;
    const int g  = h >> 2;                    // NREP = 4
    const int qi0 = blockIdx.x * 64;

    const float* Q = q + ((size_t)(b * NHEADS + h) * SEQ) * HD;
    const float* K = k + ((size_t)(b * NKV + g) * SEQ) * HD;
    const float* V = v + ((size_t)(b * NKV + g) * SEQ) * HD;

    // Load Q tile (64x64 = 1024 float4)
#pragma unroll
    for (int r = 0; r < 4; r++) {
        int idx = tid + r * 256;
        int qr = idx >> 4;
        int c4 = idx & 15;
        *(float4*)&Qs[qr][c4 * 4] =
            *(const float4*)&Q[(size_t)(qi0 + qr) * HD + c4 * 4];
    }

    float o[4][4];
#pragma unroll
    for (int i = 0; i < 4; i++)
#pragma unroll
        for (int j = 0; j < 4; j++) o[i][j] = 0.f;
    float mi[4] = {-INFINITY, -INFINITY, -INFINITY, -INFINITY};
    float li[4] = {0.f, 0.f, 0.f, 0.f};

    const int ntiles = blockIdx.x + 1;
    const float scale = 0.125f;   // 64^-0.5

    for (int t = 0; t < ntiles; t++) {
        const int kj0 = t * 64;
        __syncthreads();   // prior iter's reads of KVs/Ps done

        // Load K tile transposed: KVs[d][col]
#pragma unroll
        for (int r = 0; r < 4; r++) {
            int idx = tid + r * 256;
            int kr = idx >> 4;
            int c4 = idx & 15;
            float4 vv = *(const float4*)&K[(size_t)(kj0 + kr) * HD + c4 * 4];
            KVs[c4 * 4 + 0][kr] = vv.x;
            KVs[c4 * 4 + 1][kr] = vv.y;
            KVs[c4 * 4 + 2][kr] = vv.z;
            KVs[c4 * 4 + 3][kr] = vv.w;
        }
        __syncthreads();

        // S = Q K^T for 4x4 sub-tile
        float s[4][4];
#pragma unroll
        for (int i = 0; i < 4; i++)
#pragma unroll
            for (int j = 0; j < 4; j++) s[i][j] = 0.f;

        for (int d4 = 0; d4 < 16; d4++) {
#pragma unroll
            for (int dd = 0; dd < 4; dd++) {
                int d = d4 * 4 + dd;
                float4 kv = *(const float4*)&KVs[d][tn * 4];
                float qv0 = Qs[tm * 4 + 0][d];
                float qv1 = Qs[tm * 4 + 1][d];
                float qv2 = Qs[tm * 4 + 2][d];
                float qv3 = Qs[tm * 4 + 3][d];
                s[0][0] += qv0 * kv.x; s[0][1] += qv0 * kv.y; s[0][2] += qv0 * kv.z; s[0][3] += qv0 * kv.w;
                s[1][0] += qv1 * kv.x; s[1][1] += qv1 * kv.y; s[1][2] += qv1 * kv.z; s[1][3] += qv1 * kv.w;
                s[2][0] += qv2 * kv.x; s[2][1] += qv2 * kv.y; s[2][2] += qv2 * kv.z; s[2][3] += qv2 * kv.w;
                s[3][0] += qv3 * kv.x; s[3][1] += qv3 * kv.y; s[3][2] += qv3 * kv.z; s[3][3] += qv3 * kv.w;
            }
        }

        const bool diag = (t == blockIdx.x);
#pragma unroll
        for (int i = 0; i < 4; i++) {
#pragma unroll
            for (int j = 0; j < 4; j++) {
                s[i][j] *= scale;
                if (diag && (kj0 + tn * 4 + j) > (qi0 + tm * 4 + i))
                    s[i][j] = -INFINITY;
            }
        }

        // Online softmax update (16 lanes per row-group)
#pragma unroll
        for (int i = 0; i < 4; i++) {
            float rm = fmaxf(fmaxf(s[i][0], s[i][1]), fmaxf(s[i][2], s[i][3]));
#pragma unroll
            for (int m = 1; m < 16; m <<= 1)
                rm = fmaxf(rm, __shfl_xor_sync(0xffffffffu, rm, m));
            float nm = fmaxf(mi[i], rm);
            float alpha = __expf(mi[i] - nm);
            float rs = 0.f;
#pragma unroll
            for (int j = 0; j < 4; j++) {
                float p = __expf(s[i][j] - nm);
                Ps[tm * 4 + i][tn * 4 + j] = p;
                rs += p;
            }
#pragma unroll
            for (int m = 1; m < 16; m <<= 1)
                rs += __shfl_xor_sync(0xffffffffu, rs, m);
            li[i] = li[i] * alpha + rs;
            mi[i] = nm;
#pragma unroll
            for (int j = 0; j < 4; j++) o[i][j] *= alpha;
        }
        __syncthreads();   // S-phase reads of KVs done; Ps visible

        // Load V tile: KVs[row][d]
#pragma unroll
        for (int r = 0; r < 4; r++) {
            int idx = tid + r * 256;
            int vr = idx >> 4;
            int c4 = idx & 15;
            *(float4*)&KVs[vr][c4 * 4] =
                *(const float4*)&V[(size_t)(kj0 + vr) * HD + c4 * 4];
        }
        __syncthreads();

        // O += P V
        for (int jj = 0; jj < 64; jj++) {
            float4 vv = *(const float4*)&KVs[jj][tn * 4];
            float p0 = Ps[tm * 4 + 0][jj];
            float p1 = Ps[tm * 4 + 1][jj];
            float p2 = Ps[tm * 4 + 2][jj];
            float p3 = Ps[tm * 4 + 3][jj];
            o[0][0] += p0 * vv.x; o[0][1] += p0 * vv.y; o[0][2] += p0 * vv.z; o[0][3] += p0 * vv.w;
            o[1][0] += p1 * vv.x; o[1][1] += p1 * vv.y; o[1][2] += p1 * vv.z; o[1][3] += p1 * vv.w;
            o[2][0] += p2 * vv.x; o[2][1] += p2 * vv.y; o[2][2] += p2 * vv.z; o[2][3] += p2 * vv.w;
            o[3][0] += p3 * vv.x; o[3][1] += p3 * vv.y; o[3][2] += p3 * vv.z; o[3][3] += p3 * vv.w;
        }
    }

    // Write ctx: [b*s, h*64 + d]
#pragma unroll
    for (int i = 0; i < 4; i++) {
        int r = qi0 + tm * 4 + i;
        float inv = 1.0f / li[i];
#pragma unroll
        for (int j = 0; j < 4; j++) {
            ctx[((size_t)(b * SEQ + r)) * DOUT + h * HD + tn * 4 + j] = o[i][j] * inv;
        }
    }
}

// ----------------------------------------------------------------------------
// Launch
// Inputs: 0:x 1:mask 2:cos 3:sin 4:wq 5:wk 6:wv 7:wo 8:bo
// ----------------------------------------------------------------------------
extern "C" void kernel_launch(void* const* d_in, const int* in_sizes, int n_in,
                              void* d_out, int out_size)
{
    const float* x    = (const float*)d_in[0];
    const float* cosT = (const float*)d_in[2];
    const float* sinT = (const float*)d_in[3];
    const float* wq   = (const float*)d_in[4];
    const float* wk   = (const float*)d_in[5];
    const float* wv   = (const float*)d_in[6];
    const float* wo   = (const float*)d_in[7];
    const float* bo   = (const float*)d_in[8];
    float* out = (float*)d_out;

    float *q, *k, *v, *ctx;
    cudaGetSymbolAddress((void**)&q,   g_q);
    cudaGetSymbolAddress((void**)&k,   g_k);
    cudaGetSymbolAddress((void**)&v,   g_v);
    cudaGetSymbolAddress((void**)&ctx, g_ctx);

    // QKV projections (scatter to [b,h,s,d])
    gemm128_kernel<<<dim3(DOUT / 128, MROWS / 128), 256>>>(x, wq, q, DOUT, NHEADS, nullptr, 0);
    gemm128_kernel<<<dim3((NKV * HD) / 128, MROWS / 128), 256>>>(x, wk, k, NKV * HD, NKV, nullptr, 0);
    gemm128_kernel<<<dim3((NKV * HD) / 128, MROWS / 128), 256>>>(x, wv, v, NKV * HD, NKV, nullptr, 0);

    // RoPE on q and k
    {
        int tq = BATCH * NHEADS * SEQ * 32;
        rope_kernel<<<(tq + 255) / 256, 256>>>(q, cosT, sinT, BATCH * NHEADS);
        int tk = BATCH * NKV * SEQ * 32;
        rope_kernel<<<(tk + 255) / 256, 256>>>(k, cosT, sinT, BATCH * NKV);
    }

    // Attention
    attn_kernel<<<dim3(SEQ / 64, BATCH * NHEADS), 256>>>(q, k, v, ctx);

    // Output projection + bias
    gemm128_kernel<<<dim3(DOUT / 128, MROWS / 128), 256>>>(ctx, wo, out, DOUT, 0, bo, 1);
}

// round 3
// speedup vs baseline: 1.4609x; 1.4609x over previous
#include <cuda_runtime.h>
#include <cuda_bf16.h>
#include <math.h>
#include <stdint.h>

// Problem constants
#define BATCH   2
#define SEQ     2048
#define DIN     2048
#define DOUT    2048
#define NHEADS  32
#define NKV     8
#define HD      64
#define NREP    4
#define MROWS   (BATCH * SEQ)      // 4096

// Scratch (allocation-free rule: __device__ globals)
__device__ float g_q[(size_t)BATCH * NHEADS * SEQ * HD];   // [b,h,s,d] 32MB
__device__ float g_k[(size_t)BATCH * NKV * SEQ * HD];      // [b,g,s,d]  8MB
__device__ float g_v[(size_t)BATCH * NKV * SEQ * HD];      //            8MB
__device__ float g_ctx[(size_t)MROWS * DOUT];              // [b*s, h*d] 32MB

// ----------------------------------------------------------------------------
// tf32 helpers
// ----------------------------------------------------------------------------
__device__ __forceinline__ float to_tf32(float x) {
    uint32_t u;
    asm("cvt.rna.tf32.f32 %0, %1;" : "=r"(u) : "f"(x));
    return __uint_as_float(u);
}

__device__ __forceinline__ void mma_tf32(float c[4],
                                         uint32_t a0, uint32_t a1, uint32_t a2, uint32_t a3,
                                         uint32_t b0, uint32_t b1) {
    asm volatile(
        "mma.sync.aligned.m16n8k8.row.col.f32.tf32.tf32.f32 "
        "{%0,%1,%2,%3}, {%4,%5,%6,%7}, {%8,%9}, {%0,%1,%2,%3};"
        : "+f"(c[0]), "+f"(c[1]), "+f"(c[2]), "+f"(c[3])
        : "r"(a0), "r"(a1), "r"(a2), "r"(a3), "r"(b0), "r"(b1));
}

// ----------------------------------------------------------------------------
// tf32 tensor-core GEMM: C[M=4096, N] = A[4096, 2048(K)] * W[2048, N]
// 128x128 block tile, BK=16, double-buffered smem, 8 warps (2M x 4N),
// warp tile 64x32 (4x4 m16n8k8 mma tiles).
// mode 0: scatter to [b, h, s, d] layout (Hh heads). mode 1: row-major + bias.
// ----------------------------------------------------------------------------
#define BM 128
#define BN 128
#define BK 16
#define APAD 20    // floats per A smem row  (row-major [m][k])
#define BPAD 136   // floats per B smem row  (row-major [k][n])

__global__ __launch_bounds__(256, 1)
void gemm_tf32_kernel(const float* __restrict__ A, const float* __restrict__ W,
                      float* __restrict__ out, int N, int Hh,
                      const float* __restrict__ bias, int mode)
{
    __shared__ float As[2][BM][APAD];   // 20,480 B
    __shared__ float Bs[2][BK][BPAD];   // 17,408 B

    const int tid  = threadIdx.x;
    const int wid  = tid >> 5;
    const int lane = tid & 31;
    const int g    = lane >> 2;   // 0..7
    const int t    = lane & 3;    // 0..3

    const int warp_m = wid & 1;         // 0..1 -> 64-row slab
    const int warp_n = wid >> 1;        // 0..3 -> 32-col slab

    const int row0 = blockIdx.y * BM;
    const int col0 = blockIdx.x * BN;

    // Global load indexing (per chunk: A 128x16, B 16x128; 2 float4 each)
    const int a_r0 = tid >> 2;                 // rows 0..63 (+64)
    const int a_c4 = tid & 3;
    const int b_r0 = tid >> 5;                 // rows 0..7 (+8)
    const int b_c4 = tid & 31;

    float c[4][4][4];
#pragma unroll
    for (int i = 0; i < 4; i++)
#pragma unroll
        for (int j = 0; j < 4; j++)
#pragma unroll
            for (int r = 0; r < 4; r++) c[i][j][r] = 0.f;

    float4 ra[2], rb[2];

    auto load_chunk = [&](int k0) {
#pragma unroll
        for (int r = 0; r < 2; r++) {
            int ar = a_r0 + r * 64;
            ra[r] = *(const float4*)&A[(size_t)(row0 + ar) * DIN + k0 + a_c4 * 4];
            int br = b_r0 + r * 8;
            rb[r] = *(const float4*)&W[(size_t)(k0 + br) * N + col0 + b_c4 * 4];
        }
    };
    auto store_chunk = [&](int buf) {
#pragma unroll
        for (int r = 0; r < 2; r++) {
            int ar = a_r0 + r * 64;
            float4 va = ra[r];
            va.x = to_tf32(va.x); va.y = to_tf32(va.y);
            va.z = to_tf32(va.z); va.w = to_tf32(va.w);
            *(float4*)&As[buf][ar][a_c4 * 4] = va;
            int br = b_r0 + r * 8;
            float4 vb = rb[r];
            vb.x = to_tf32(vb.x); vb.y = to_tf32(vb.y);
            vb.z = to_tf32(vb.z); vb.w = to_tf32(vb.w);
            *(float4*)&Bs[buf][br][b_c4 * 4] = vb;
        }
    };

    // Prologue
    load_chunk(0);
    store_chunk(0);
    __syncthreads();

    int buf = 0;
    const int NCHUNK = DIN / BK;   // 128
    for (int kc = 0; kc < NCHUNK; kc++) {
        if (kc + 1 < NCHUNK) load_chunk((kc + 1) * BK);

        // Compute from smem[buf]
#pragma unroll
        for (int ks = 0; ks < 2; ks++) {
            const int kb = ks * 8;
            uint32_t af[4][4];
#pragma unroll
            for (int mt = 0; mt < 4; mt++) {
                int rb_ = warp_m * 64 + mt * 16;
                af[mt][0] = __float_as_uint(As[buf][rb_ + g    ][kb + t    ]);
                af[mt][1] = __float_as_uint(As[buf][rb_ + g + 8][kb + t    ]);
                af[mt][2] = __float_as_uint(As[buf][rb_ + g    ][kb + t + 4]);
                af[mt][3] = __float_as_uint(As[buf][rb_ + g + 8][kb + t + 4]);
            }
            uint32_t bf[4][2];
#pragma unroll
            for (int nt = 0; nt < 4; nt++) {
                int cb = warp_n * 32 + nt * 8 + g;
                bf[nt][0] = __float_as_uint(Bs[buf][kb + t    ][cb]);
                bf[nt][1] = __float_as_uint(Bs[buf][kb + t + 4][cb]);
            }
#pragma unroll
            for (int mt = 0; mt < 4; mt++)
#pragma unroll
                for (int nt = 0; nt < 4; nt++)
                    mma_tf32(c[mt][nt], af[mt][0], af[mt][1], af[mt][2], af[mt][3],
                             bf[nt][0], bf[nt][1]);
        }

        if (kc + 1 < NCHUNK) store_chunk(buf ^ 1);
        __syncthreads();
        buf ^= 1;
    }

    // Epilogue
#pragma unroll
    for (int mt = 0; mt < 4; mt++) {
        int rbase = row0 + warp_m * 64 + mt * 16;
#pragma unroll
        for (int nt = 0; nt < 4; nt++) {
            int cbase = col0 + warp_n * 32 + nt * 8;
#pragma unroll
            for (int half = 0; half < 2; half++) {
                int r = rbase + g + half * 8;
                float v0 = c[mt][nt][half * 2 + 0];
                float v1 = c[mt][nt][half * 2 + 1];
                int n0 = cbase + t * 2;
                if (mode == 0) {
                    int b = r >> 11;
                    int s = r & 2047;
                    int h = n0 >> 6;
                    int d = n0 & 63;
                    float* p = &out[(((size_t)(b * Hh + h)) * SEQ + s) * HD + d];
                    p[0] = v0;
                    p[1] = v1;   // d even, so d+1 stays in same head
                } else {
                    float2 o;
                    o.x = v0 + bias[n0];
                    o.y = v1 + bias[n0 + 1];
                    *(float2*)&out[(size_t)r * N + n0] = o;
                }
            }
        }
    }
}

// ----------------------------------------------------------------------------
// RoPE (in-place on [BH, S, 64])
// ----------------------------------------------------------------------------
__global__ void rope_kernel(float* __restrict__ buf,
                            const float* __restrict__ cosT,
                            const float* __restrict__ sinT, int BH)
{
    int idx = blockIdx.x * blockDim.x + threadIdx.x;
    int total = BH * SEQ * 32;
    if (idx >= total) return;
    int d  = idx & 31;
    int s  = (idx >> 5) & (SEQ - 1);
    int bh = idx >> 16;
    float* p = buf + ((size_t)bh * SEQ + s) * HD;
    float t1 = p[d];
    float t2 = p[d + 32];
    float cv = cosT[s * HD + d];
    float sv = sinT[s * HD + d];
    p[d]      = t1 * cv - t2 * sv;
    p[d + 32] = t2 * cv + t1 * sv;
}

// ----------------------------------------------------------------------------
// Flash attention (fp32), 64x64 tiles. Grid: (S/64, B*NHEADS).
// ----------------------------------------------------------------------------
__global__ __launch_bounds__(256)
void attn_kernel(const float* __restrict__ q, const float* __restrict__ k,
                 const float* __restrict__ v, float* __restrict__ ctx)
{
    __shared__ float Qs[64][64];
    __shared__ float KVs[64][64];
    __shared__ float Ps[64][64];

    const int tid = threadIdx.x;
    const int tm = tid >> 4;
    const int tn = tid & 15;

    const int bh = blockIdx.y;
    const int b  = bh >> 5;
    const int h  = bh & 31;
    const int g  = h >> 2;
    const int qi0 = blockIdx.x * 64;

    const float* Q = q + ((size_t)(b * NHEADS + h) * SEQ) * HD;
    const float* K = k + ((size_t)(b * NKV + g) * SEQ) * HD;
    const float* V = v + ((size_t)(b * NKV + g) * SEQ) * HD;

#pragma unroll
    for (int r = 0; r < 4; r++) {
        int idx = tid + r * 256;
        int qr = idx >> 4;
        int c4 = idx & 15;
        *(float4*)&Qs[qr][c4 * 4] =
            *(const float4*)&Q[(size_t)(qi0 + qr) * HD + c4 * 4];
    }

    float o[4][4];
#pragma unroll
    for (int i = 0; i < 4; i++)
#pragma unroll
        for (int j = 0; j < 4; j++) o[i][j] = 0.f;
    float mi[4] = {-INFINITY, -INFINITY, -INFINITY, -INFINITY};
    float li[4] = {0.f, 0.f, 0.f, 0.f};

    const int ntiles = blockIdx.x + 1;
    const float scale = 0.125f;

    for (int tt = 0; tt < ntiles; tt++) {
        const int kj0 = tt * 64;
        __syncthreads();

#pragma unroll
        for (int r = 0; r < 4; r++) {
            int idx = tid + r * 256;
            int kr = idx >> 4;
            int c4 = idx & 15;
            float4 vv = *(const float4*)&K[(size_t)(kj0 + kr) * HD + c4 * 4];
            KVs[c4 * 4 + 0][kr] = vv.x;
            KVs[c4 * 4 + 1][kr] = vv.y;
            KVs[c4 * 4 + 2][kr] = vv.z;
            KVs[c4 * 4 + 3][kr] = vv.w;
        }
        __syncthreads();

        float s[4][4];
#pragma unroll
        for (int i = 0; i < 4; i++)
#pragma unroll
            for (int j = 0; j < 4; j++) s[i][j] = 0.f;

        for (int d4 = 0; d4 < 16; d4++) {
#pragma unroll
            for (int dd = 0; dd < 4; dd++) {
                int d = d4 * 4 + dd;
                float4 kv = *(const float4*)&KVs[d][tn * 4];
                float qv0 = Qs[tm * 4 + 0][d];
                float qv1 = Qs[tm * 4 + 1][d];
                float qv2 = Qs[tm * 4 + 2][d];
                float qv3 = Qs[tm * 4 + 3][d];
                s[0][0] += qv0 * kv.x; s[0][1] += qv0 * kv.y; s[0][2] += qv0 * kv.z; s[0][3] += qv0 * kv.w;
                s[1][0] += qv1 * kv.x; s[1][1] += qv1 * kv.y; s[1][2] += qv1 * kv.z; s[1][3] += qv1 * kv.w;
                s[2][0] += qv2 * kv.x; s[2][1] += qv2 * kv.y; s[2][2] += qv2 * kv.z; s[2][3] += qv2 * kv.w;
                s[3][0] += qv3 * kv.x; s[3][1] += qv3 * kv.y; s[3][2] += qv3 * kv.z; s[3][3] += qv3 * kv.w;
            }
        }

        const bool diag = (tt == blockIdx.x);
#pragma unroll
        for (int i = 0; i < 4; i++) {
#pragma unroll
            for (int j = 0; j < 4; j++) {
                s[i][j] *= scale;
                if (diag && (kj0 + tn * 4 + j) > (qi0 + tm * 4 + i))
                    s[i][j] = -INFINITY;
            }
        }

#pragma unroll
        for (int i = 0; i < 4; i++) {
            float rm = fmaxf(fmaxf(s[i][0], s[i][1]), fmaxf(s[i][2], s[i][3]));
#pragma unroll
            for (int m = 1; m < 16; m <<= 1)
                rm = fmaxf(rm, __shfl_xor_sync(0xffffffffu, rm, m));
            float nm = fmaxf(mi[i], rm);
            float alpha = __expf(mi[i] - nm);
            float rs = 0.f;
#pragma unroll
            for (int j = 0; j < 4; j++) {
                float p = __expf(s[i][j] - nm);
                Ps[tm * 4 + i][tn * 4 + j] = p;
                rs += p;
            }
#pragma unroll
            for (int m = 1; m < 16; m <<= 1)
                rs += __shfl_xor_sync(0xffffffffu, rs, m);
            li[i] = li[i] * alpha + rs;
            mi[i] = nm;
#pragma unroll
            for (int j = 0; j < 4; j++) o[i][j] *= alpha;
        }
        __syncthreads();

#pragma unroll
        for (int r = 0; r < 4; r++) {
            int idx = tid + r * 256;
            int vr = idx >> 4;
            int c4 = idx & 15;
            *(float4*)&KVs[vr][c4 * 4] =
                *(const float4*)&V[(size_t)(kj0 + vr) * HD + c4 * 4];
        }
        __syncthreads();

        for (int jj = 0; jj < 64; jj++) {
            float4 vv = *(const float4*)&KVs[jj][tn * 4];
            float p0 = Ps[tm * 4 + 0][jj];
            float p1 = Ps[tm * 4 + 1][jj];
            float p2 = Ps[tm * 4 + 2][jj];
            float p3 = Ps[tm * 4 + 3][jj];
            o[0][0] += p0 * vv.x; o[0][1] += p0 * vv.y; o[0][2] += p0 * vv.z; o[0][3] += p0 * vv.w;
            o[1][0] += p1 * vv.x; o[1][1] += p1 * vv.y; o[1][2] += p1 * vv.z; o[1][3] += p1 * vv.w;
            o[2][0] += p2 * vv.x; o[2][1] += p2 * vv.y; o[2][2] += p2 * vv.z; o[2][3] += p2 * vv.w;
            o[3][0] += p3 * vv.x; o[3][1] += p3 * vv.y; o[3][2] += p3 * vv.z; o[3][3] += p3 * vv.w;
        }
    }

#pragma unroll
    for (int i = 0; i < 4; i++) {
        int r = qi0 + tm * 4 + i;
        float inv = 1.0f / li[i];
#pragma unroll
        for (int j = 0; j < 4; j++) {
            ctx[((size_t)(b * SEQ + r)) * DOUT + h * HD + tn * 4 + j] = o[i][j] * inv;
        }
    }
}

// ----------------------------------------------------------------------------
// Launch.  Inputs: 0:x 1:mask 2:cos 3:sin 4:wq 5:wk 6:wv 7:wo 8:bo
// ----------------------------------------------------------------------------
extern "C" void kernel_launch(void* const* d_in, const int* in_sizes, int n_in,
                              void* d_out, int out_size)
{
    const float* x    = (const float*)d_in[0];
    const float* cosT = (const float*)d_in[2];
    const float* sinT = (const float*)d_in[3];
    const float* wq   = (const float*)d_in[4];
    const float* wk   = (const float*)d_in[5];
    const float* wv   = (const float*)d_in[6];
    const float* wo   = (const float*)d_in[7];
    const float* bo   = (const float*)d_in[8];
    float* out = (float*)d_out;

    float *q, *k, *v, *ctx;
    cudaGetSymbolAddress((void**)&q,   g_q);
    cudaGetSymbolAddress((void**)&k,   g_k);
    cudaGetSymbolAddress((void**)&v,   g_v);
    cudaGetSymbolAddress((void**)&ctx, g_ctx);

    // QKV projections (tf32 tensor cores, scatter to [b,h,s,d])
    gemm_tf32_kernel<<<dim3(DOUT / BN, MROWS / BM), 256>>>(x, wq, q, DOUT, NHEADS, nullptr, 0);
    gemm_tf32_kernel<<<dim3((NKV * HD) / BN, MROWS / BM), 256>>>(x, wk, k, NKV * HD, NKV, nullptr, 0);
    gemm_tf32_kernel<<<dim3((NKV * HD) / BN, MROWS / BM), 256>>>(x, wv, v, NKV * HD, NKV, nullptr, 0);

    // RoPE on q and k
    {
        int tq = BATCH * NHEADS * SEQ * 32;
        rope_kernel<<<(tq + 255) / 256, 256>>>(q, cosT, sinT, BATCH * NHEADS);
        int tk = BATCH * NKV * SEQ * 32;
        rope_kernel<<<(tk + 255) / 256, 256>>>(k, cosT, sinT, BATCH * NKV);
    }

    // Attention (fp32 — tensor-core conversion is next round's change)
    attn_kernel<<<dim3(SEQ / 64, BATCH * NHEADS), 256>>>(q, k, v, ctx);

    // Output projection + bias (tf32 tensor cores)
    gemm_tf32_kernel<<<dim3(DOUT / BN, MROWS / BM), 256>>>(ctx, wo, out, DOUT, 0, bo, 1);
}

// round 4
// speedup vs baseline: 2.5131x; 1.7202x over previous
#include <cuda_runtime.h>
#include <cuda_bf16.h>
#include <math.h>
#include <stdint.h>

// Problem constants
#define BATCH   2
#define SEQ     2048
#define DIN     2048
#define DOUT    2048
#define NHEADS  32
#define NKV     8
#define HD      64
#define NREP    4
#define MROWS   (BATCH * SEQ)      // 4096

// Scratch (allocation-free rule: __device__ globals)
__device__ float g_q[(size_t)BATCH * NHEADS * SEQ * HD];   // [b,h,s,d] 32MB
__device__ float g_k[(size_t)BATCH * NKV * SEQ * HD];      // [b,g,s,d]  8MB
__device__ float g_v[(size_t)BATCH * NKV * SEQ * HD];      //            8MB
__device__ float g_ctx[(size_t)MROWS * DOUT];              // [b*s, h*d] 32MB

// ----------------------------------------------------------------------------
// tf32 helpers
// ----------------------------------------------------------------------------
__device__ __forceinline__ float to_tf32(float x) {
    uint32_t u;
    asm("cvt.rna.tf32.f32 %0, %1;" : "=r"(u) : "f"(x));
    return __uint_as_float(u);
}

__device__ __forceinline__ void mma_tf32(float c[4],
                                         uint32_t a0, uint32_t a1, uint32_t a2, uint32_t a3,
                                         uint32_t b0, uint32_t b1) {
    asm volatile(
        "mma.sync.aligned.m16n8k8.row.col.f32.tf32.tf32.f32 "
        "{%0,%1,%2,%3}, {%4,%5,%6,%7}, {%8,%9}, {%0,%1,%2,%3};"
        : "+f"(c[0]), "+f"(c[1]), "+f"(c[2]), "+f"(c[3])
        : "r"(a0), "r"(a1), "r"(a2), "r"(a3), "r"(b0), "r"(b1));
}

// ----------------------------------------------------------------------------
// tf32 tensor-core GEMM (unchanged from round 3 — passing at rel_err 5e-4)
// ----------------------------------------------------------------------------
#define BM 128
#define BN 128
#define BK 16
#define APAD 20
#define BPAD 136

__global__ __launch_bounds__(256, 1)
void gemm_tf32_kernel(const float* __restrict__ A, const float* __restrict__ W,
                      float* __restrict__ out, int N, int Hh,
                      const float* __restrict__ bias, int mode)
{
    __shared__ float As[2][BM][APAD];
    __shared__ float Bs[2][BK][BPAD];

    const int tid  = threadIdx.x;
    const int wid  = tid >> 5;
    const int lane = tid & 31;
    const int g    = lane >> 2;
    const int t    = lane & 3;

    const int warp_m = wid & 1;
    const int warp_n = wid >> 1;

    const int row0 = blockIdx.y * BM;
    const int col0 = blockIdx.x * BN;

    const int a_r0 = tid >> 2;
    const int a_c4 = tid & 3;
    const int b_r0 = tid >> 5;
    const int b_c4 = tid & 31;

    float c[4][4][4];
#pragma unroll
    for (int i = 0; i < 4; i++)
#pragma unroll
        for (int j = 0; j < 4; j++)
#pragma unroll
            for (int r = 0; r < 4; r++) c[i][j][r] = 0.f;

    float4 ra[2], rb[2];

    auto load_chunk = [&](int k0) {
#pragma unroll
        for (int r = 0; r < 2; r++) {
            int ar = a_r0 + r * 64;
            ra[r] = *(const float4*)&A[(size_t)(row0 + ar) * DIN + k0 + a_c4 * 4];
            int br = b_r0 + r * 8;
            rb[r] = *(const float4*)&W[(size_t)(k0 + br) * N + col0 + b_c4 * 4];
        }
    };
    auto store_chunk = [&](int buf) {
#pragma unroll
        for (int r = 0; r < 2; r++) {
            int ar = a_r0 + r * 64;
            float4 va = ra[r];
            va.x = to_tf32(va.x); va.y = to_tf32(va.y);
            va.z = to_tf32(va.z); va.w = to_tf32(va.w);
            *(float4*)&As[buf][ar][a_c4 * 4] = va;
            int br = b_r0 + r * 8;
            float4 vb = rb[r];
            vb.x = to_tf32(vb.x); vb.y = to_tf32(vb.y);
            vb.z = to_tf32(vb.z); vb.w = to_tf32(vb.w);
            *(float4*)&Bs[buf][br][b_c4 * 4] = vb;
        }
    };

    load_chunk(0);
    store_chunk(0);
    __syncthreads();

    int buf = 0;
    const int NCHUNK = DIN / BK;
    for (int kc = 0; kc < NCHUNK; kc++) {
        if (kc + 1 < NCHUNK) load_chunk((kc + 1) * BK);

#pragma unroll
        for (int ks = 0; ks < 2; ks++) {
            const int kb = ks * 8;
            uint32_t af[4][4];
#pragma unroll
            for (int mt = 0; mt < 4; mt++) {
                int rb_ = warp_m * 64 + mt * 16;
                af[mt][0] = __float_as_uint(As[buf][rb_ + g    ][kb + t    ]);
                af[mt][1] = __float_as_uint(As[buf][rb_ + g + 8][kb + t    ]);
                af[mt][2] = __float_as_uint(As[buf][rb_ + g    ][kb + t + 4]);
                af[mt][3] = __float_as_uint(As[buf][rb_ + g + 8][kb + t + 4]);
            }
            uint32_t bf[4][2];
#pragma unroll
            for (int nt = 0; nt < 4; nt++) {
                int cb = warp_n * 32 + nt * 8 + g;
                bf[nt][0] = __float_as_uint(Bs[buf][kb + t    ][cb]);
                bf[nt][1] = __float_as_uint(Bs[buf][kb + t + 4][cb]);
            }
#pragma unroll
            for (int mt = 0; mt < 4; mt++)
#pragma unroll
                for (int nt = 0; nt < 4; nt++)
                    mma_tf32(c[mt][nt], af[mt][0], af[mt][1], af[mt][2], af[mt][3],
                             bf[nt][0], bf[nt][1]);
        }

        if (kc + 1 < NCHUNK) store_chunk(buf ^ 1);
        __syncthreads();
        buf ^= 1;
    }

#pragma unroll
    for (int mt = 0; mt < 4; mt++) {
        int rbase = row0 + warp_m * 64 + mt * 16;
#pragma unroll
        for (int nt = 0; nt < 4; nt++) {
            int cbase = col0 + warp_n * 32 + nt * 8;
#pragma unroll
            for (int half = 0; half < 2; half++) {
                int r = rbase + g + half * 8;
                float v0 = c[mt][nt][half * 2 + 0];
                float v1 = c[mt][nt][half * 2 + 1];
                int n0 = cbase + t * 2;
                if (mode == 0) {
                    int b = r >> 11;
                    int s = r & 2047;
                    int h = n0 >> 6;
                    int d = n0 & 63;
                    float* p = &out[(((size_t)(b * Hh + h)) * SEQ + s) * HD + d];
                    p[0] = v0;
                    p[1] = v1;
                } else {
                    float2 o;
                    o.x = v0 + bias[n0];
                    o.y = v1 + bias[n0 + 1];
                    *(float2*)&out[(size_t)r * N + n0] = o;
                }
            }
        }
    }
}

// ----------------------------------------------------------------------------
// RoPE (in-place on [BH, S, 64])
// ----------------------------------------------------------------------------
__global__ void rope_kernel(float* __restrict__ buf,
                            const float* __restrict__ cosT,
                            const float* __restrict__ sinT, int BH)
{
    int idx = blockIdx.x * blockDim.x + threadIdx.x;
    int total = BH * SEQ * 32;
    if (idx >= total) return;
    int d  = idx & 31;
    int s  = (idx >> 5) & (SEQ - 1);
    int bh = idx >> 16;
    float* p = buf + ((size_t)bh * SEQ + s) * HD;
    float t1 = p[d];
    float t2 = p[d + 32];
    float cv = cosT[s * HD + d];
    float sv = sinT[s * HD + d];
    p[d]      = t1 * cv - t2 * sv;
    p[d + 32] = t2 * cv + t1 * sv;
}

// ----------------------------------------------------------------------------
// Tensor-core flash attention (tf32 mma, fp32 softmax state).
// Block: 128 q-rows, 8 warps (each owns a 16-row strip). K/V tiles of 64.
// Grid: (SEQ/128, BATCH*NHEADS). Dynamic smem.
// ----------------------------------------------------------------------------
#define QPAD 68   // floats per smem row: 4g+t bank pattern conflict-free

__global__ __launch_bounds__(256, 2)
void attn_tc_kernel(const float* __restrict__ q, const float* __restrict__ k,
                    const float* __restrict__ v, float* __restrict__ ctx)
{
    extern __shared__ float sm[];
    float* Qs = sm;                    // [128][QPAD]
    float* Ps = Qs + 128 * QPAD;       // [128][QPAD]  (S then P)
    float* Ks = Ps + 128 * QPAD;       // [64][QPAD]
    float* Vs = Ks + 64 * QPAD;        // [64][QPAD]
    float* mi = Vs + 64 * QPAD;        // [128]
    float* li = mi + 128;              // [128]
    float* al = li + 128;              // [128]

    const int tid  = threadIdx.x;
    const int wid  = tid >> 5;
    const int lane = tid & 31;
    const int g    = lane >> 2;
    const int t    = lane & 3;

    const int bh = blockIdx.y;
    const int b  = bh >> 5;
    const int h  = bh & 31;
    const int kvg = h >> 2;
    const int qi0 = blockIdx.x * 128;
    const int mb  = wid * 16;          // this warp's row strip

    const float* Q = q + ((size_t)(b * NHEADS + h)  * SEQ) * HD;
    const float* K = k + ((size_t)(b * NKV + kvg)   * SEQ) * HD;
    const float* V = v + ((size_t)(b * NKV + kvg)   * SEQ) * HD;

    // Load Q tile (128x64), tf32-rounded
#pragma unroll
    for (int r = 0; r < 8; r++) {
        int idx = tid + r * 256;
        int qr = idx >> 4;
        int c4 = idx & 15;
        float4 vv = *(const float4*)&Q[(size_t)(qi0 + qr) * HD + c4 * 4];
        vv.x = to_tf32(vv.x); vv.y = to_tf32(vv.y);
        vv.z = to_tf32(vv.z); vv.w = to_tf32(vv.w);
        *(float4*)&Qs[qr * QPAD + c4 * 4] = vv;
    }
    if (tid < 128) { mi[tid] = -INFINITY; li[tid] = 0.f; }

    float o[8][4];
#pragma unroll
    for (int n = 0; n < 8; n++)
#pragma unroll
        for (int r = 0; r < 4; r++) o[n][r] = 0.f;

    const int ntiles = 2 * blockIdx.x + 2;
    const float scale = 0.125f;    // 64^-0.5

    for (int tt = 0; tt < ntiles; tt++) {
        const int kj0 = tt * 64;
        __syncthreads();   // prior O-mma reads of Ks/Vs/Ps complete

        // Load K and V tiles (64x64 each), tf32-rounded
#pragma unroll
        for (int r = 0; r < 4; r++) {
            int idx = tid + r * 256;
            int kr = idx >> 4;
            int c4 = idx & 15;
            float4 a = *(const float4*)&K[(size_t)(kj0 + kr) * HD + c4 * 4];
            a.x = to_tf32(a.x); a.y = to_tf32(a.y);
            a.z = to_tf32(a.z); a.w = to_tf32(a.w);
            *(float4*)&Ks[kr * QPAD + c4 * 4] = a;
            float4 bb = *(const float4*)&V[(size_t)(kj0 + kr) * HD + c4 * 4];
            bb.x = to_tf32(bb.x); bb.y = to_tf32(bb.y);
            bb.z = to_tf32(bb.z); bb.w = to_tf32(bb.w);
            *(float4*)&Vs[kr * QPAD + c4 * 4] = bb;
        }
        __syncthreads();

        // S = Q K^T : warp's 16x64 strip, 8 n-tiles, 8 k-steps
        float sfr[8][4];
#pragma unroll
        for (int n = 0; n < 8; n++)
#pragma unroll
            for (int r = 0; r < 4; r++) sfr[n][r] = 0.f;

#pragma unroll
        for (int kk = 0; kk < 8; kk++) {
            const int kb = kk * 8;
            uint32_t a0 = __float_as_uint(Qs[(mb + g    ) * QPAD + kb + t    ]);
            uint32_t a1 = __float_as_uint(Qs[(mb + g + 8) * QPAD + kb + t    ]);
            uint32_t a2 = __float_as_uint(Qs[(mb + g    ) * QPAD + kb + t + 4]);
            uint32_t a3 = __float_as_uint(Qs[(mb + g + 8) * QPAD + kb + t + 4]);
#pragma unroll
            for (int n = 0; n < 8; n++) {
                const int nb = n * 8;
                uint32_t b0 = __float_as_uint(Ks[(nb + g) * QPAD + kb + t    ]);
                uint32_t b1 = __float_as_uint(Ks[(nb + g) * QPAD + kb + t + 4]);
                mma_tf32(sfr[n], a0, a1, a2, a3, b0, b1);
            }
        }

        // Stage S to smem (Ps buffer)
#pragma unroll
        for (int n = 0; n < 8; n++) {
            const int nb = n * 8;
            float2 lo = make_float2(sfr[n][0], sfr[n][1]);
            float2 hi = make_float2(sfr[n][2], sfr[n][3]);
            *(float2*)&Ps[(mb + g    ) * QPAD + nb + 2 * t] = lo;
            *(float2*)&Ps[(mb + g + 8) * QPAD + nb + 2 * t] = hi;
        }
        __syncthreads();

        // Softmax: 2 threads per row (32 cols each)
        {
            const int row  = tid >> 1;
            const int half = tid & 1;
            const int qrow = qi0 + row;
            float* prow = Ps + row * QPAD + half * 32;
            const int kbase = kj0 + half * 32;
            int nvalid = qrow - kbase + 1;
            if (nvalid < 0) nvalid = 0;
            if (nvalid > 32) nvalid = 32;

            float rm = -INFINITY;
            for (int j = 0; j < nvalid; j++)
                rm = fmaxf(rm, prow[j] * scale);
            rm = fmaxf(rm, __shfl_xor_sync(0xffffffffu, rm, 1));

            float mold = mi[row];
            float nm = fmaxf(mold, rm);
            float alpha = __expf(mold - nm);
            float rs = 0.f;
            for (int j = 0; j < nvalid; j++) {
                float p = __expf(prow[j] * scale - nm);
                rs += p;
                prow[j] = to_tf32(p);
            }
            for (int j = nvalid; j < 32; j++) prow[j] = 0.f;
            rs += __shfl_xor_sync(0xffffffffu, rs, 1);
            if (half == 0) {
                li[row] = li[row] * alpha + rs;
                mi[row] = nm;
                al[row] = alpha;
            }
        }
        __syncthreads();

        // O = O*alpha + P V
        {
            float alpha0 = al[mb + g];
            float alpha1 = al[mb + g + 8];
#pragma unroll
            for (int n = 0; n < 8; n++) {
                o[n][0] *= alpha0; o[n][1] *= alpha0;
                o[n][2] *= alpha1; o[n][3] *= alpha1;
            }
#pragma unroll
            for (int kk = 0; kk < 8; kk++) {
                const int kb = kk * 8;
                uint32_t a0 = __float_as_uint(Ps[(mb + g    ) * QPAD + kb + t    ]);
                uint32_t a1 = __float_as_uint(Ps[(mb + g + 8) * QPAD + kb + t    ]);
                uint32_t a2 = __float_as_uint(Ps[(mb + g    ) * QPAD + kb + t + 4]);
                uint32_t a3 = __float_as_uint(Ps[(mb + g + 8) * QPAD + kb + t + 4]);
#pragma unroll
                for (int n = 0; n < 8; n++) {
                    const int nb = n * 8;
                    uint32_t b0 = __float_as_uint(Vs[(kb + t    ) * QPAD + nb + g]);
                    uint32_t b1 = __float_as_uint(Vs[(kb + t + 4) * QPAD + nb + g]);
                    mma_tf32(o[n], a0, a1, a2, a3, b0, b1);
                }
            }
        }
    }

    // Epilogue: normalize and write ctx [b*s, h*64+d]
    {
        float inv0 = 1.0f / li[mb + g];
        float inv1 = 1.0f / li[mb + g + 8];
        int row0 = qi0 + mb + g;
        int row1 = row0 + 8;
#pragma unroll
        for (int n = 0; n < 8; n++) {
            int col = h * HD + n * 8 + 2 * t;
            float2 v0 = make_float2(o[n][0] * inv0, o[n][1] * inv0);
            float2 v1 = make_float2(o[n][2] * inv1, o[n][3] * inv1);
            *(float2*)&ctx[((size_t)(b * SEQ + row0)) * DOUT + col] = v0;
            *(float2*)&ctx[((size_t)(b * SEQ + row1)) * DOUT + col] = v1;
        }
    }
}

// ----------------------------------------------------------------------------
// Launch.  Inputs: 0:x 1:mask 2:cos 3:sin 4:wq 5:wk 6:wv 7:wo 8:bo
// ----------------------------------------------------------------------------
#define ATTN_SMEM_BYTES ((384 * QPAD + 384) * 4)

extern "C" void kernel_launch(void* const* d_in, const int* in_sizes, int n_in,
                              void* d_out, int out_size)
{
    const float* x    = (const float*)d_in[0];
    const float* cosT = (const float*)d_in[2];
    const float* sinT = (const float*)d_in[3];
    const float* wq   = (const float*)d_in[4];
    const float* wk   = (const float*)d_in[5];
    const float* wv   = (const float*)d_in[6];
    const float* wo   = (const float*)d_in[7];
    const float* bo   = (const float*)d_in[8];
    float* out = (float*)d_out;

    float *q, *k, *v, *ctx;
    cudaGetSymbolAddress((void**)&q,   g_q);
    cudaGetSymbolAddress((void**)&k,   g_k);
    cudaGetSymbolAddress((void**)&v,   g_v);
    cudaGetSymbolAddress((void**)&ctx, g_ctx);

    cudaFuncSetAttribute(attn_tc_kernel,
                         cudaFuncAttributeMaxDynamicSharedMemorySize, ATTN_SMEM_BYTES);

    // QKV projections (tf32 tensor cores, scatter to [b,h,s,d])
    gemm_tf32_kernel<<<dim3(DOUT / BN, MROWS / BM), 256>>>(x, wq, q, DOUT, NHEADS, nullptr, 0);
    gemm_tf32_kernel<<<dim3((NKV * HD) / BN, MROWS / BM), 256>>>(x, wk, k, NKV * HD, NKV, nullptr, 0);
    gemm_tf32_kernel<<<dim3((NKV * HD) / BN, MROWS / BM), 256>>>(x, wv, v, NKV * HD, NKV, nullptr, 0);

    // RoPE on q and k
    {
        int tq = BATCH * NHEADS * SEQ * 32;
        rope_kernel<<<(tq + 255) / 256, 256>>>(q, cosT, sinT, BATCH * NHEADS);
        int tk = BATCH * NKV * SEQ * 32;
        rope_kernel<<<(tk + 255) / 256, 256>>>(k, cosT, sinT, BATCH * NKV);
    }

    // Tensor-core flash attention
    attn_tc_kernel<<<dim3(SEQ / 128, BATCH * NHEADS), 256, ATTN_SMEM_BYTES>>>(q, k, v, ctx);

    // Output projection + bias (tf32 tensor cores)
    gemm_tf32_kernel<<<dim3(DOUT / BN, MROWS / BM), 256>>>(ctx, wo, out, DOUT, 0, bo, 1);
}

// round 7
// speedup vs baseline: 2.6832x; 1.0677x over previous
#include <cuda_runtime.h>
#include <cuda_bf16.h>
#include <math.h>
#include <stdint.h>

// Problem constants
#define BATCH   2
#define SEQ     2048
#define DIN     2048
#define DOUT    2048
#define NHEADS  32
#define NKV     8
#define HD      64
#define NREP    4
#define MROWS   (BATCH * SEQ)      // 4096
#define NKVD    (NKV * HD)         // 512

// Scratch (allocation-free rule: __device__ globals)
__device__ float g_q[(size_t)BATCH * NHEADS * SEQ * HD];   // [b,h,s,d] 32MB
__device__ float g_k[(size_t)BATCH * NKV * SEQ * HD];      // [b,g,s,d]  8MB
__device__ float g_v[(size_t)BATCH * NKV * SEQ * HD];      //            8MB
__device__ float g_ctx[(size_t)MROWS * DOUT];              // [b*s, h*d] 32MB

// ----------------------------------------------------------------------------
// tf32 / cp.async helpers
// ----------------------------------------------------------------------------
__device__ __forceinline__ float to_tf32(float x) {
    uint32_t u;
    asm("cvt.rna.tf32.f32 %0, %1;" : "=r"(u) : "f"(x));
    return __uint_as_float(u);
}

__device__ __forceinline__ uint32_t ld_tf32(const float* p) {
    uint32_t u;
    asm("cvt.rna.tf32.f32 %0, %1;" : "=r"(u) : "f"(*p));
    return u;
}

__device__ __forceinline__ void mma_tf32(float c[4],
                                         uint32_t a0, uint32_t a1, uint32_t a2, uint32_t a3,
                                         uint32_t b0, uint32_t b1) {
    asm volatile(
        "mma.sync.aligned.m16n8k8.row.col.f32.tf32.tf32.f32 "
        "{%0,%1,%2,%3}, {%4,%5,%6,%7}, {%8,%9}, {%0,%1,%2,%3};"
        : "+f"(c[0]), "+f"(c[1]), "+f"(c[2]), "+f"(c[3])
        : "r"(a0), "r"(a1), "r"(a2), "r"(a3), "r"(b0), "r"(b1));
}

__device__ __forceinline__ void cp_async16(float* smem_dst, const float* gsrc) {
    uint32_t s = (uint32_t)__cvta_generic_to_shared(smem_dst);
    asm volatile("cp.async.cg.shared.global [%0], [%1], 16;\n" :: "r"(s), "l"(gsrc));
}
__device__ __forceinline__ void cp_commit() {
    asm volatile("cp.async.commit_group;\n");
}
template <int N>
__device__ __forceinline__ void cp_wait() {
    asm volatile("cp.async.wait_group %0;\n" :: "n"(N));
}

// ----------------------------------------------------------------------------
// Pipelined tf32 GEMM: C[M=4096, N] = A[4096, 2048] * W[2048, N]
// 3-stage cp.async pipeline, BK=16, 8 warps (2M x 4N), warp tile 64x32.
// Fused QKV via per-block weight/output selection (boundaries 128-aligned).
// mode 0: scatter to [b, h, s, d]. mode 1: row-major + bias.
// (Resubmission: rounds 5 & 6 died to broker failures before execution;
//  audit found no group-accounting, alignment, OOB, or divergence issue.)
// ----------------------------------------------------------------------------
#define BM 128
#define BN 128
#define BK 16
#define APADF 20
#define BPADF 136
#define A_STAGE (BM * APADF)                 // 2560 floats
#define B_STAGE (BK * BPADF)                 // 2176 floats
#define STAGE_FLOATS (A_STAGE + B_STAGE)     // 4736 floats
#define GEMM_STAGES 3
#define GEMM_SMEM_BYTES (GEMM_STAGES * STAGE_FLOATS * 4)   // 56,832 B

__global__ __launch_bounds__(256, 1)
void gemm_pipe_kernel(const float* __restrict__ A,
                      const float* __restrict__ W0, const float* __restrict__ W1,
                      const float* __restrict__ W2,
                      float* __restrict__ out0, float* __restrict__ out1,
                      float* __restrict__ out2,
                      const float* __restrict__ bias, int mode)
{
    extern __shared__ float smp[];

    const int tid  = threadIdx.x;
    const int wid  = tid >> 5;
    const int lane = tid & 31;
    const int g    = lane >> 2;
    const int t    = lane & 3;
    const int warp_m = wid & 1;
    const int warp_n = wid >> 1;

    const int row0  = blockIdx.y * BM;
    const int col0g = blockIdx.x * BN;

    // Per-block matrix selection (QKV fusion). mode 1 always uses W0.
    const float* W;
    float* outp;
    int Nmat, Hh, coll;
    if (mode == 1 || col0g < DOUT)      { W = W0; outp = out0; Nmat = DOUT; Hh = NHEADS; coll = col0g; }
    else if (col0g < DOUT + NKVD)       { W = W1; outp = out1; Nmat = NKVD; Hh = NKV;    coll = col0g - DOUT; }
    else                                { W = W2; outp = out2; Nmat = NKVD; Hh = NKV;    coll = col0g - DOUT - NKVD; }

    const int a_r0 = tid >> 2;    // + 64
    const int a_c  = tid & 3;
    const int b_r0 = tid >> 5;    // + 8
    const int b_c  = tid & 31;

    auto issue_load = [&](int stage, int kc) {
        const int k0 = kc * BK;
        float* As = smp + stage * STAGE_FLOATS;
        float* Bs = As + A_STAGE;
#pragma unroll
        for (int r = 0; r < 2; r++) {
            int ar = a_r0 + r * 64;
            cp_async16(&As[ar * APADF + a_c * 4],
                       &A[(size_t)(row0 + ar) * DIN + k0 + a_c * 4]);
            int br = b_r0 + r * 8;
            cp_async16(&Bs[br * BPADF + b_c * 4],
                       &W[(size_t)(k0 + br) * Nmat + coll + b_c * 4]);
        }
    };

    float c[4][4][4];
#pragma unroll
    for (int i = 0; i < 4; i++)
#pragma unroll
        for (int j = 0; j < 4; j++)
#pragma unroll
            for (int r = 0; r < 4; r++) c[i][j][r] = 0.f;

    // Prologue: fill 2 stages
    issue_load(0, 0); cp_commit();
    issue_load(1, 1); cp_commit();

    const int NCHUNK = DIN / BK;   // 128
    int stage = 0;
    for (int kc = 0; kc < NCHUNK; kc++) {
        cp_wait<1>();
        __syncthreads();

        // Start load for kc+2 into the stage freed at iteration kc-1
        if (kc + 2 < NCHUNK) issue_load((stage + 2) % GEMM_STAGES, kc + 2);
        cp_commit();

        const float* As = smp + stage * STAGE_FLOATS;
        const float* Bs = As + A_STAGE;

#pragma unroll
        for (int ks = 0; ks < 2; ks++) {
            const int kb = ks * 8;
            uint32_t af[4][4];
#pragma unroll
            for (int mt = 0; mt < 4; mt++) {
                int rb_ = warp_m * 64 + mt * 16;
                af[mt][0] = ld_tf32(&As[(rb_ + g    ) * APADF + kb + t    ]);
                af[mt][1] = ld_tf32(&As[(rb_ + g + 8) * APADF + kb + t    ]);
                af[mt][2] = ld_tf32(&As[(rb_ + g    ) * APADF + kb + t + 4]);
                af[mt][3] = ld_tf32(&As[(rb_ + g + 8) * APADF + kb + t + 4]);
            }
            uint32_t bf[4][2];
#pragma unroll
            for (int nt = 0; nt < 4; nt++) {
                int cb = warp_n * 32 + nt * 8 + g;
                bf[nt][0] = ld_tf32(&Bs[(kb + t    ) * BPADF + cb]);
                bf[nt][1] = ld_tf32(&Bs[(kb + t + 4) * BPADF + cb]);
            }
#pragma unroll
            for (int mt = 0; mt < 4; mt++)
#pragma unroll
                for (int nt = 0; nt < 4; nt++)
                    mma_tf32(c[mt][nt], af[mt][0], af[mt][1], af[mt][2], af[mt][3],
                             bf[nt][0], bf[nt][1]);
        }

        __syncthreads();
        stage = (stage + 1) % GEMM_STAGES;
    }

    // Epilogue
#pragma unroll
    for (int mt = 0; mt < 4; mt++) {
        int rbase = row0 + warp_m * 64 + mt * 16;
#pragma unroll
        for (int nt = 0; nt < 4; nt++) {
            int cbase = coll + warp_n * 32 + nt * 8;
#pragma unroll
            for (int half = 0; half < 2; half++) {
                int r = rbase + g + half * 8;
                float v0 = c[mt][nt][half * 2 + 0];
                float v1 = c[mt][nt][half * 2 + 1];
                int n0 = cbase + t * 2;
                if (mode == 0) {
                    int b = r >> 11;
                    int s = r & 2047;
                    int h = n0 >> 6;
                    int d = n0 & 63;
                    float* p = &outp[(((size_t)(b * Hh + h)) * SEQ + s) * HD + d];
                    p[0] = v0;
                    p[1] = v1;   // d even, same head
                } else {
                    float2 o;
                    o.x = v0 + bias[n0];
                    o.y = v1 + bias[n0 + 1];
                    *(float2*)&outp[(size_t)r * DOUT + n0] = o;
                }
            }
        }
    }
}

// ----------------------------------------------------------------------------
// RoPE (in-place on [BH, S, 64])
// ----------------------------------------------------------------------------
__global__ void rope_kernel(float* __restrict__ buf,
                            const float* __restrict__ cosT,
                            const float* __restrict__ sinT, int BH)
{
    int idx = blockIdx.x * blockDim.x + threadIdx.x;
    int total = BH * SEQ * 32;
    if (idx >= total) return;
    int d  = idx & 31;
    int s  = (idx >> 5) & (SEQ - 1);
    int bh = idx >> 16;
    float* p = buf + ((size_t)bh * SEQ + s) * HD;
    float t1 = p[d];
    float t2 = p[d + 32];
    float cv = cosT[s * HD + d];
    float sv = sinT[s * HD + d];
    p[d]      = t1 * cv - t2 * sv;
    p[d + 32] = t2 * cv + t1 * sv;
}

// ----------------------------------------------------------------------------
// Tensor-core flash attention (unchanged — passing at 6.1e-4)
// ----------------------------------------------------------------------------
#define QPAD 68

__global__ __launch_bounds__(256, 2)
void attn_tc_kernel(const float* __restrict__ q, const float* __restrict__ k,
                    const float* __restrict__ v, float* __restrict__ ctx)
{
    extern __shared__ float sm[];
    float* Qs = sm;                    // [128][QPAD]
    float* Ps = Qs + 128 * QPAD;       // [128][QPAD]
    float* Ks = Ps + 128 * QPAD;       // [64][QPAD]
    float* Vs = Ks + 64 * QPAD;        // [64][QPAD]
    float* mi = Vs + 64 * QPAD;        // [128]
    float* li = mi + 128;              // [128]
    float* al = li + 128;              // [128]

    const int tid  = threadIdx.x;
    const int wid  = tid >> 5;
    const int lane = tid & 31;
    const int g    = lane >> 2;
    const int t    = lane & 3;

    const int bh = blockIdx.y;
    const int b  = bh >> 5;
    const int h  = bh & 31;
    const int kvg = h >> 2;
    const int qi0 = blockIdx.x * 128;
    const int mb  = wid * 16;

    const float* Q = q + ((size_t)(b * NHEADS + h)  * SEQ) * HD;
    const float* K = k + ((size_t)(b * NKV + kvg)   * SEQ) * HD;
    const float* V = v + ((size_t)(b * NKV + kvg)   * SEQ) * HD;

#pragma unroll
    for (int r = 0; r < 8; r++) {
        int idx = tid + r * 256;
        int qr = idx >> 4;
        int c4 = idx & 15;
        float4 vv = *(const float4*)&Q[(size_t)(qi0 + qr) * HD + c4 * 4];
        vv.x = to_tf32(vv.x); vv.y = to_tf32(vv.y);
        vv.z = to_tf32(vv.z); vv.w = to_tf32(vv.w);
        *(float4*)&Qs[qr * QPAD + c4 * 4] = vv;
    }
    if (tid < 128) { mi[tid] = -INFINITY; li[tid] = 0.f; }

    float o[8][4];
#pragma unroll
    for (int n = 0; n < 8; n++)
#pragma unroll
        for (int r = 0; r < 4; r++) o[n][r] = 0.f;

    const int ntiles = 2 * blockIdx.x + 2;
    const float scale = 0.125f;

    for (int tt = 0; tt < ntiles; tt++) {
        const int kj0 = tt * 64;
        __syncthreads();

#pragma unroll
        for (int r = 0; r < 4; r++) {
            int idx = tid + r * 256;
            int kr = idx >> 4;
            int c4 = idx & 15;
            float4 a = *(const float4*)&K[(size_t)(kj0 + kr) * HD + c4 * 4];
            a.x = to_tf32(a.x); a.y = to_tf32(a.y);
            a.z = to_tf32(a.z); a.w = to_tf32(a.w);
            *(float4*)&Ks[kr * QPAD + c4 * 4] = a;
            float4 bb = *(const float4*)&V[(size_t)(kj0 + kr) * HD + c4 * 4];
            bb.x = to_tf32(bb.x); bb.y = to_tf32(bb.y);
            bb.z = to_tf32(bb.z); bb.w = to_tf32(bb.w);
            *(float4*)&Vs[kr * QPAD + c4 * 4] = bb;
        }
        __syncthreads();

        float sfr[8][4];
#pragma unroll
        for (int n = 0; n < 8; n++)
#pragma unroll
            for (int r = 0; r < 4; r++) sfr[n][r] = 0.f;

#pragma unroll
        for (int kk = 0; kk < 8; kk++) {
            const int kb = kk * 8;
            uint32_t a0 = __float_as_uint(Qs[(mb + g    ) * QPAD + kb + t    ]);
            uint32_t a1 = __float_as_uint(Qs[(mb + g + 8) * QPAD + kb + t    ]);
            uint32_t a2 = __float_as_uint(Qs[(mb + g    ) * QPAD + kb + t + 4]);
            uint32_t a3 = __float_as_uint(Qs[(mb + g + 8) * QPAD + kb + t + 4]);
#pragma unroll
            for (int n = 0; n < 8; n++) {
                const int nb = n * 8;
                uint32_t b0 = __float_as_uint(Ks[(nb + g) * QPAD + kb + t    ]);
                uint32_t b1 = __float_as_uint(Ks[(nb + g) * QPAD + kb + t + 4]);
                mma_tf32(sfr[n], a0, a1, a2, a3, b0, b1);
            }
        }

#pragma unroll
        for (int n = 0; n < 8; n++) {
            const int nb = n * 8;
            float2 lo = make_float2(sfr[n][0], sfr[n][1]);
            float2 hi = make_float2(sfr[n][2], sfr[n][3]);
            *(float2*)&Ps[(mb + g    ) * QPAD + nb + 2 * t] = lo;
            *(float2*)&Ps[(mb + g + 8) * QPAD + nb + 2 * t] = hi;
        }
        __syncthreads();

        {
            const int row  = tid >> 1;
            const int half = tid & 1;
            const int qrow = qi0 + row;
            float* prow = Ps + row * QPAD + half * 32;
            const int kbase = kj0 + half * 32;
            int nvalid = qrow - kbase + 1;
            if (nvalid < 0) nvalid = 0;
            if (nvalid > 32) nvalid = 32;

            float rm = -INFINITY;
            for (int j = 0; j < nvalid; j++)
                rm = fmaxf(rm, prow[j] * scale);
            rm = fmaxf(rm, __shfl_xor_sync(0xffffffffu, rm, 1));

            float mold = mi[row];
            float nm = fmaxf(mold, rm);
            float alpha = __expf(mold - nm);
            float rs = 0.f;
            for (int j = 0; j < nvalid; j++) {
                float p = __expf(prow[j] * scale - nm);
                rs += p;
                prow[j] = to_tf32(p);
            }
            for (int j = nvalid; j < 32; j++) prow[j] = 0.f;
            rs += __shfl_xor_sync(0xffffffffu, rs, 1);
            if (half == 0) {
                li[row] = li[row] * alpha + rs;
                mi[row] = nm;
                al[row] = alpha;
            }
        }
        __syncthreads();

        {
            float alpha0 = al[mb + g];
            float alpha1 = al[mb + g + 8];
#pragma unroll
            for (int n = 0; n < 8; n++) {
                o[n][0] *= alpha0; o[n][1] *= alpha0;
                o[n][2] *= alpha1; o[n][3] *= alpha1;
            }
#pragma unroll
            for (int kk = 0; kk < 8; kk++) {
                const int kb = kk * 8;
                uint32_t a0 = __float_as_uint(Ps[(mb + g    ) * QPAD + kb + t    ]);
                uint32_t a1 = __float_as_uint(Ps[(mb + g + 8) * QPAD + kb + t    ]);
                uint32_t a2 = __float_as_uint(Ps[(mb + g    ) * QPAD + kb + t + 4]);
                uint32_t a3 = __float_as_uint(Ps[(mb + g + 8) * QPAD + kb + t + 4]);
#pragma unroll
                for (int n = 0; n < 8; n++) {
                    const int nb = n * 8;
                    uint32_t b0 = __float_as_uint(Vs[(kb + t    ) * QPAD + nb + g]);
                    uint32_t b1 = __float_as_uint(Vs[(kb + t + 4) * QPAD + nb + g]);
                    mma_tf32(o[n], a0, a1, a2, a3, b0, b1);
                }
            }
        }
    }

    {
        float inv0 = 1.0f / li[mb + g];
        float inv1 = 1.0f / li[mb + g + 8];
        int row0 = qi0 + mb + g;
        int row1 = row0 + 8;
#pragma unroll
        for (int n = 0; n < 8; n++) {
            int col = h * HD + n * 8 + 2 * t;
            float2 v0 = make_float2(o[n][0] * inv0, o[n][1] * inv0);
            float2 v1 = make_float2(o[n][2] * inv1, o[n][3] * inv1);
            *(float2*)&ctx[((size_t)(b * SEQ + row0)) * DOUT + col] = v0;
            *(float2*)&ctx[((size_t)(b * SEQ + row1)) * DOUT + col] = v1;
        }
    }
}

// ----------------------------------------------------------------------------
// Launch.  Inputs: 0:x 1:mask 2:cos 3:sin 4:wq 5:wk 6:wv 7:wo 8:bo
// ----------------------------------------------------------------------------
#define ATTN_SMEM_BYTES ((384 * QPAD + 384) * 4)

extern "C" void kernel_launch(void* const* d_in, const int* in_sizes, int n_in,
                              void* d_out, int out_size)
{
    const float* x    = (const float*)d_in[0];
    const float* cosT = (const float*)d_in[2];
    const float* sinT = (const float*)d_in[3];
    const float* wq   = (const float*)d_in[4];
    const float* wk   = (const float*)d_in[5];
    const float* wv   = (const float*)d_in[6];
    const float* wo   = (const float*)d_in[7];
    const float* bo   = (const float*)d_in[8];
    float* out = (float*)d_out;

    float *q, *k, *v, *ctx;
    cudaGetSymbolAddress((void**)&q,   g_q);
    cudaGetSymbolAddress((void**)&k,   g_k);
    cudaGetSymbolAddress((void**)&v,   g_v);
    cudaGetSymbolAddress((void**)&ctx, g_ctx);

    cudaFuncSetAttribute(gemm_pipe_kernel,
                         cudaFuncAttributeMaxDynamicSharedMemorySize, GEMM_SMEM_BYTES);
    cudaFuncSetAttribute(attn_tc_kernel,
                         cudaFuncAttributeMaxDynamicSharedMemorySize, ATTN_SMEM_BYTES);

    // Fused QKV projection (one launch, N = 2048 + 512 + 512)
    gemm_pipe_kernel<<<dim3((DOUT + 2 * NKVD) / BN, MROWS / BM), 256, GEMM_SMEM_BYTES>>>(
        x, wq, wk, wv, q, k, v, nullptr, 0);

    // RoPE on q and k
    {
        int tq = BATCH * NHEADS * SEQ * 32;
        rope_kernel<<<(tq + 255) / 256, 256>>>(q, cosT, sinT, BATCH * NHEADS);
        int tk = BATCH * NKV * SEQ * 32;
        rope_kernel<<<(tk + 255) / 256, 256>>>(k, cosT, sinT, BATCH * NKV);
    }

    // Tensor-core flash attention
    attn_tc_kernel<<<dim3(SEQ / 128, BATCH * NHEADS), 256, ATTN_SMEM_BYTES>>>(q, k, v, ctx);

    // Output projection + bias
    gemm_pipe_kernel<<<dim3(DOUT / BN, MROWS / BM), 256, GEMM_SMEM_BYTES>>>(
        ctx, wo, nullptr, nullptr, out, nullptr, nullptr, bo, 1);
}

// round 8
// speedup vs baseline: 2.9220x; 1.0890x over previous
#include <cuda_runtime.h>
#include <cuda_bf16.h>
#include <math.h>
#include <stdint.h>

// Problem constants
#define BATCH   2
#define SEQ     2048
#define DIN     2048
#define DOUT    2048
#define NHEADS  32
#define NKV     8
#define HD      64
#define NREP    4
#define MROWS   (BATCH * SEQ)      // 4096
#define NKVD    (NKV * HD)         // 512

// Scratch (allocation-free rule: __device__ globals)
__device__ float g_q[(size_t)BATCH * NHEADS * SEQ * HD];   // [b,h,s,d] 32MB
__device__ float g_k[(size_t)BATCH * NKV * SEQ * HD];      // [b,g,s,d]  8MB
__device__ float g_v[(size_t)BATCH * NKV * SEQ * HD];      //            8MB
__device__ float g_ctx[(size_t)MROWS * DOUT];              // [b*s, h*d] 32MB

// ----------------------------------------------------------------------------
// tf32 / cp.async helpers
// ----------------------------------------------------------------------------
__device__ __forceinline__ float to_tf32(float x) {
    uint32_t u;
    asm("cvt.rna.tf32.f32 %0, %1;" : "=r"(u) : "f"(x));
    return __uint_as_float(u);
}

__device__ __forceinline__ uint32_t ld_tf32(const float* p) {
    uint32_t u;
    asm("cvt.rna.tf32.f32 %0, %1;" : "=r"(u) : "f"(*p));
    return u;
}

__device__ __forceinline__ void mma_tf32(float c[4],
                                         uint32_t a0, uint32_t a1, uint32_t a2, uint32_t a3,
                                         uint32_t b0, uint32_t b1) {
    asm volatile(
        "mma.sync.aligned.m16n8k8.row.col.f32.tf32.tf32.f32 "
        "{%0,%1,%2,%3}, {%4,%5,%6,%7}, {%8,%9}, {%0,%1,%2,%3};"
        : "+f"(c[0]), "+f"(c[1]), "+f"(c[2]), "+f"(c[3])
        : "r"(a0), "r"(a1), "r"(a2), "r"(a3), "r"(b0), "r"(b1));
}

__device__ __forceinline__ void cp_async16(float* smem_dst, const float* gsrc) {
    uint32_t s = (uint32_t)__cvta_generic_to_shared(smem_dst);
    asm volatile("cp.async.cg.shared.global [%0], [%1], 16;\n" :: "r"(s), "l"(gsrc));
}
__device__ __forceinline__ void cp_commit() {
    asm volatile("cp.async.commit_group;\n");
}
template <int N>
__device__ __forceinline__ void cp_wait() {
    asm volatile("cp.async.wait_group %0;\n" :: "n"(N));
}

// ----------------------------------------------------------------------------
// Pipelined tf32 GEMM (unchanged from round 7 — passing, ~93 TF/s)
// ----------------------------------------------------------------------------
#define BM 128
#define BN 128
#define BK 16
#define APADF 20
#define BPADF 136
#define A_STAGE (BM * APADF)
#define B_STAGE (BK * BPADF)
#define STAGE_FLOATS (A_STAGE + B_STAGE)
#define GEMM_STAGES 3
#define GEMM_SMEM_BYTES (GEMM_STAGES * STAGE_FLOATS * 4)   // 56,832 B

__global__ __launch_bounds__(256, 1)
void gemm_pipe_kernel(const float* __restrict__ A,
                      const float* __restrict__ W0, const float* __restrict__ W1,
                      const float* __restrict__ W2,
                      float* __restrict__ out0, float* __restrict__ out1,
                      float* __restrict__ out2,
                      const float* __restrict__ bias, int mode)
{
    extern __shared__ float smp[];

    const int tid  = threadIdx.x;
    const int wid  = tid >> 5;
    const int lane = tid & 31;
    const int g    = lane >> 2;
    const int t    = lane & 3;
    const int warp_m = wid & 1;
    const int warp_n = wid >> 1;

    const int row0  = blockIdx.y * BM;
    const int col0g = blockIdx.x * BN;

    const float* W;
    float* outp;
    int Nmat, Hh, coll;
    if (mode == 1 || col0g < DOUT)      { W = W0; outp = out0; Nmat = DOUT; Hh = NHEADS; coll = col0g; }
    else if (col0g < DOUT + NKVD)       { W = W1; outp = out1; Nmat = NKVD; Hh = NKV;    coll = col0g - DOUT; }
    else                                { W = W2; outp = out2; Nmat = NKVD; Hh = NKV;    coll = col0g - DOUT - NKVD; }

    const int a_r0 = tid >> 2;
    const int a_c  = tid & 3;
    const int b_r0 = tid >> 5;
    const int b_c  = tid & 31;

    auto issue_load = [&](int stage, int kc) {
        const int k0 = kc * BK;
        float* As = smp + stage * STAGE_FLOATS;
        float* Bs = As + A_STAGE;
#pragma unroll
        for (int r = 0; r < 2; r++) {
            int ar = a_r0 + r * 64;
            cp_async16(&As[ar * APADF + a_c * 4],
                       &A[(size_t)(row0 + ar) * DIN + k0 + a_c * 4]);
            int br = b_r0 + r * 8;
            cp_async16(&Bs[br * BPADF + b_c * 4],
                       &W[(size_t)(k0 + br) * Nmat + coll + b_c * 4]);
        }
    };

    float c[4][4][4];
#pragma unroll
    for (int i = 0; i < 4; i++)
#pragma unroll
        for (int j = 0; j < 4; j++)
#pragma unroll
            for (int r = 0; r < 4; r++) c[i][j][r] = 0.f;

    issue_load(0, 0); cp_commit();
    issue_load(1, 1); cp_commit();

    const int NCHUNK = DIN / BK;
    int stage = 0;
    for (int kc = 0; kc < NCHUNK; kc++) {
        cp_wait<1>();
        __syncthreads();

        if (kc + 2 < NCHUNK) issue_load((stage + 2) % GEMM_STAGES, kc + 2);
        cp_commit();

        const float* As = smp + stage * STAGE_FLOATS;
        const float* Bs = As + A_STAGE;

#pragma unroll
        for (int ks = 0; ks < 2; ks++) {
            const int kb = ks * 8;
            uint32_t af[4][4];
#pragma unroll
            for (int mt = 0; mt < 4; mt++) {
                int rb_ = warp_m * 64 + mt * 16;
                af[mt][0] = ld_tf32(&As[(rb_ + g    ) * APADF + kb + t    ]);
                af[mt][1] = ld_tf32(&As[(rb_ + g + 8) * APADF + kb + t    ]);
                af[mt][2] = ld_tf32(&As[(rb_ + g    ) * APADF + kb + t + 4]);
                af[mt][3] = ld_tf32(&As[(rb_ + g + 8) * APADF + kb + t + 4]);
            }
            uint32_t bf[4][2];
#pragma unroll
            for (int nt = 0; nt < 4; nt++) {
                int cb = warp_n * 32 + nt * 8 + g;
                bf[nt][0] = ld_tf32(&Bs[(kb + t    ) * BPADF + cb]);
                bf[nt][1] = ld_tf32(&Bs[(kb + t + 4) * BPADF + cb]);
            }
#pragma unroll
            for (int mt = 0; mt < 4; mt++)
#pragma unroll
                for (int nt = 0; nt < 4; nt++)
                    mma_tf32(c[mt][nt], af[mt][0], af[mt][1], af[mt][2], af[mt][3],
                             bf[nt][0], bf[nt][1]);
        }

        __syncthreads();
        stage = (stage + 1) % GEMM_STAGES;
    }

#pragma unroll
    for (int mt = 0; mt < 4; mt++) {
        int rbase = row0 + warp_m * 64 + mt * 16;
#pragma unroll
        for (int nt = 0; nt < 4; nt++) {
            int cbase = coll + warp_n * 32 + nt * 8;
#pragma unroll
            for (int half = 0; half < 2; half++) {
                int r = rbase + g + half * 8;
                float v0 = c[mt][nt][half * 2 + 0];
                float v1 = c[mt][nt][half * 2 + 1];
                int n0 = cbase + t * 2;
                if (mode == 0) {
                    int b = r >> 11;
                    int s = r & 2047;
                    int h = n0 >> 6;
                    int d = n0 & 63;
                    float* p = &outp[(((size_t)(b * Hh + h)) * SEQ + s) * HD + d];
                    p[0] = v0;
                    p[1] = v1;
                } else {
                    float2 o;
                    o.x = v0 + bias[n0];
                    o.y = v1 + bias[n0 + 1];
                    *(float2*)&outp[(size_t)r * DOUT + n0] = o;
                }
            }
        }
    }
}

// ----------------------------------------------------------------------------
// RoPE (in-place on [BH, S, 64])
// ----------------------------------------------------------------------------
__global__ void rope_kernel(float* __restrict__ buf,
                            const float* __restrict__ cosT,
                            const float* __restrict__ sinT, int BH)
{
    int idx = blockIdx.x * blockDim.x + threadIdx.x;
    int total = BH * SEQ * 32;
    if (idx >= total) return;
    int d  = idx & 31;
    int s  = (idx >> 5) & (SEQ - 1);
    int bh = idx >> 16;
    float* p = buf + ((size_t)bh * SEQ + s) * HD;
    float t1 = p[d];
    float t2 = p[d + 32];
    float cv = cosT[s * HD + d];
    float sv = sinT[s * HD + d];
    p[d]      = t1 * cv - t2 * sv;
    p[d + 32] = t2 * cv + t1 * sv;
}

// ----------------------------------------------------------------------------
// Tensor-core flash attention, register-fragment softmax.
// Block: 128 q-rows, 8 warps (16-row strips). K/V tiles of 64.
// Softmax on mma C-fragments in registers (quad shfl reductions);
// Ps smem used only as the P->A-operand layout transposer (warp-private).
// ----------------------------------------------------------------------------
#define QPAD 68

__global__ __launch_bounds__(256, 2)
void attn_tc_kernel(const float* __restrict__ q, const float* __restrict__ k,
                    const float* __restrict__ v, float* __restrict__ ctx)
{
    extern __shared__ float sm[];
    float* Qs = sm;                    // [128][QPAD]
    float* Ps = Qs + 128 * QPAD;       // [128][QPAD]  (P staging, warp-private strips)
    float* Ks = Ps + 128 * QPAD;       // [64][QPAD]
    float* Vs = Ks + 64 * QPAD;        // [64][QPAD]

    const int tid  = threadIdx.x;
    const int wid  = tid >> 5;
    const int lane = tid & 31;
    const int g    = lane >> 2;
    const int t    = lane & 3;

    const int bh = blockIdx.y;
    const int b  = bh >> 5;
    const int h  = bh & 31;
    const int kvg = h >> 2;
    const int qi0 = blockIdx.x * 128;
    const int mb  = wid * 16;

    const float* Q = q + ((size_t)(b * NHEADS + h)  * SEQ) * HD;
    const float* K = k + ((size_t)(b * NKV + kvg)   * SEQ) * HD;
    const float* V = v + ((size_t)(b * NKV + kvg)   * SEQ) * HD;

    // Load Q tile (128x64), tf32-rounded
#pragma unroll
    for (int r = 0; r < 8; r++) {
        int idx = tid + r * 256;
        int qr = idx >> 4;
        int c4 = idx & 15;
        float4 vv = *(const float4*)&Q[(size_t)(qi0 + qr) * HD + c4 * 4];
        vv.x = to_tf32(vv.x); vv.y = to_tf32(vv.y);
        vv.z = to_tf32(vv.z); vv.w = to_tf32(vv.w);
        *(float4*)&Qs[qr * QPAD + c4 * 4] = vv;
    }

    // Per-thread softmax state for fragment rows (replicated across each quad)
    const int row0g = qi0 + mb + g;        // fragment row 0
    const int row1g = row0g + 8;           // fragment row 1
    float mi0 = -INFINITY, mi1 = -INFINITY;
    float li0 = 0.f, li1 = 0.f;

    float o[8][4];
#pragma unroll
    for (int n = 0; n < 8; n++)
#pragma unroll
        for (int r = 0; r < 4; r++) o[n][r] = 0.f;

    const int ntiles = 2 * blockIdx.x + 2;
    const float scale = 0.125f;

    for (int tt = 0; tt < ntiles; tt++) {
        const int kj0 = tt * 64;
        __syncthreads();   // all warps done reading Ks/Vs of previous tile

        // Load K and V tiles (64x64 each), tf32-rounded
#pragma unroll
        for (int r = 0; r < 4; r++) {
            int idx = tid + r * 256;
            int kr = idx >> 4;
            int c4 = idx & 15;
            float4 a = *(const float4*)&K[(size_t)(kj0 + kr) * HD + c4 * 4];
            a.x = to_tf32(a.x); a.y = to_tf32(a.y);
            a.z = to_tf32(a.z); a.w = to_tf32(a.w);
            *(float4*)&Ks[kr * QPAD + c4 * 4] = a;
            float4 bb = *(const float4*)&V[(size_t)(kj0 + kr) * HD + c4 * 4];
            bb.x = to_tf32(bb.x); bb.y = to_tf32(bb.y);
            bb.z = to_tf32(bb.z); bb.w = to_tf32(bb.w);
            *(float4*)&Vs[kr * QPAD + c4 * 4] = bb;
        }
        __syncthreads();

        // S = Q K^T : warp's 16x64 strip
        float sfr[8][4];
#pragma unroll
        for (int n = 0; n < 8; n++)
#pragma unroll
            for (int r = 0; r < 4; r++) sfr[n][r] = 0.f;

#pragma unroll
        for (int kk = 0; kk < 8; kk++) {
            const int kb = kk * 8;
            uint32_t a0 = __float_as_uint(Qs[(mb + g    ) * QPAD + kb + t    ]);
            uint32_t a1 = __float_as_uint(Qs[(mb + g + 8) * QPAD + kb + t    ]);
            uint32_t a2 = __float_as_uint(Qs[(mb + g    ) * QPAD + kb + t + 4]);
            uint32_t a3 = __float_as_uint(Qs[(mb + g + 8) * QPAD + kb + t + 4]);
#pragma unroll
            for (int n = 0; n < 8; n++) {
                const int nb = n * 8;
                uint32_t b0 = __float_as_uint(Ks[(nb + g) * QPAD + kb + t    ]);
                uint32_t b1 = __float_as_uint(Ks[(nb + g) * QPAD + kb + t + 4]);
                mma_tf32(sfr[n], a0, a1, a2, a3, b0, b1);
            }
        }

        // ---- Register softmax on fragments ----
        // Scale + causal mask + row max
        float rm0 = -INFINITY, rm1 = -INFINITY;
#pragma unroll
        for (int n = 0; n < 8; n++) {
            const int c0 = kj0 + n * 8 + 2 * t;
            const int c1 = c0 + 1;
            sfr[n][0] = (c0 <= row0g) ? sfr[n][0] * scale : -INFINITY;
            sfr[n][1] = (c1 <= row0g) ? sfr[n][1] * scale : -INFINITY;
            sfr[n][2] = (c0 <= row1g) ? sfr[n][2] * scale : -INFINITY;
            sfr[n][3] = (c1 <= row1g) ? sfr[n][3] * scale : -INFINITY;
            rm0 = fmaxf(rm0, fmaxf(sfr[n][0], sfr[n][1]));
            rm1 = fmaxf(rm1, fmaxf(sfr[n][2], sfr[n][3]));
        }
        rm0 = fmaxf(rm0, __shfl_xor_sync(0xffffffffu, rm0, 1));
        rm0 = fmaxf(rm0, __shfl_xor_sync(0xffffffffu, rm0, 2));
        rm1 = fmaxf(rm1, __shfl_xor_sync(0xffffffffu, rm1, 1));
        rm1 = fmaxf(rm1, __shfl_xor_sync(0xffffffffu, rm1, 2));

        const float nm0 = fmaxf(mi0, rm0);
        const float nm1 = fmaxf(mi1, rm1);
        const float al0 = __expf(mi0 - nm0);   // first tile: rows always have col 0 valid
        const float al1 = __expf(mi1 - nm1);

        // exp + row sum; P left in fragments (tf32-rounded)
        float s0 = 0.f, s1 = 0.f;
#pragma unroll
        for (int n = 0; n < 8; n++) {
            float p0 = __expf(sfr[n][0] - nm0);
            float p1 = __expf(sfr[n][1] - nm0);
            float p2 = __expf(sfr[n][2] - nm1);
            float p3 = __expf(sfr[n][3] - nm1);
            s0 += p0 + p1;
            s1 += p2 + p3;
            sfr[n][0] = to_tf32(p0);
            sfr[n][1] = to_tf32(p1);
            sfr[n][2] = to_tf32(p2);
            sfr[n][3] = to_tf32(p3);
        }
        s0 += __shfl_xor_sync(0xffffffffu, s0, 1);
        s0 += __shfl_xor_sync(0xffffffffu, s0, 2);
        s1 += __shfl_xor_sync(0xffffffffu, s1, 1);
        s1 += __shfl_xor_sync(0xffffffffu, s1, 2);

        li0 = li0 * al0 + s0;  mi0 = nm0;
        li1 = li1 * al1 + s1;  mi1 = nm1;

        // Rescale O
#pragma unroll
        for (int n = 0; n < 8; n++) {
            o[n][0] *= al0; o[n][1] *= al0;
            o[n][2] *= al1; o[n][3] *= al1;
        }

        // Stage P to (warp-private) smem strip for the A-operand layout
#pragma unroll
        for (int n = 0; n < 8; n++) {
            const int nb = n * 8;
            *(float2*)&Ps[(mb + g    ) * QPAD + nb + 2 * t] = make_float2(sfr[n][0], sfr[n][1]);
            *(float2*)&Ps[(mb + g + 8) * QPAD + nb + 2 * t] = make_float2(sfr[n][2], sfr[n][3]);
        }
        __syncwarp();   // warp-private strip: warp-level visibility suffices

        // O += P V
#pragma unroll
        for (int kk = 0; kk < 8; kk++) {
            const int kb = kk * 8;
            uint32_t a0 = __float_as_uint(Ps[(mb + g    ) * QPAD + kb + t    ]);
            uint32_t a1 = __float_as_uint(Ps[(mb + g + 8) * QPAD + kb + t    ]);
            uint32_t a2 = __float_as_uint(Ps[(mb + g    ) * QPAD + kb + t + 4]);
            uint32_t a3 = __float_as_uint(Ps[(mb + g + 8) * QPAD + kb + t + 4]);
#pragma unroll
            for (int n = 0; n < 8; n++) {
                const int nb = n * 8;
                uint32_t b0 = __float_as_uint(Vs[(kb + t    ) * QPAD + nb + g]);
                uint32_t b1 = __float_as_uint(Vs[(kb + t + 4) * QPAD + nb + g]);
                mma_tf32(o[n], a0, a1, a2, a3, b0, b1);
            }
        }
    }

    // Epilogue: normalize and write ctx [b*s, h*64+d]
    {
        const float inv0 = 1.0f / li0;
        const float inv1 = 1.0f / li1;
#pragma unroll
        for (int n = 0; n < 8; n++) {
            int col = h * HD + n * 8 + 2 * t;
            float2 v0 = make_float2(o[n][0] * inv0, o[n][1] * inv0);
            float2 v1 = make_float2(o[n][2] * inv1, o[n][3] * inv1);
            *(float2*)&ctx[((size_t)(b * SEQ + row0g)) * DOUT + col] = v0;
            *(float2*)&ctx[((size_t)(b * SEQ + row1g)) * DOUT + col] = v1;
        }
    }
}

// ----------------------------------------------------------------------------
// Launch.  Inputs: 0:x 1:mask 2:cos 3:sin 4:wq 5:wk 6:wv 7:wo 8:bo
// ----------------------------------------------------------------------------
#define ATTN_SMEM_BYTES ((384 * QPAD) * 4)

extern "C" void kernel_launch(void* const* d_in, const int* in_sizes, int n_in,
                              void* d_out, int out_size)
{
    const float* x    = (const float*)d_in[0];
    const float* cosT = (const float*)d_in[2];
    const float* sinT = (const float*)d_in[3];
    const float* wq   = (const float*)d_in[4];
    const float* wk   = (const float*)d_in[5];
    const float* wv   = (const float*)d_in[6];
    const float* wo   = (const float*)d_in[7];
    const float* bo   = (const float*)d_in[8];
    float* out = (float*)d_out;

    float *q, *k, *v, *ctx;
    cudaGetSymbolAddress((void**)&q,   g_q);
    cudaGetSymbolAddress((void**)&k,   g_k);
    cudaGetSymbolAddress((void**)&v,   g_v);
    cudaGetSymbolAddress((void**)&ctx, g_ctx);

    cudaFuncSetAttribute(gemm_pipe_kernel,
                         cudaFuncAttributeMaxDynamicSharedMemorySize, GEMM_SMEM_BYTES);
    cudaFuncSetAttribute(attn_tc_kernel,
                         cudaFuncAttributeMaxDynamicSharedMemorySize, ATTN_SMEM_BYTES);

    // Fused QKV projection (one launch, N = 2048 + 512 + 512)
    gemm_pipe_kernel<<<dim3((DOUT + 2 * NKVD) / BN, MROWS / BM), 256, GEMM_SMEM_BYTES>>>(
        x, wq, wk, wv, q, k, v, nullptr, 0);

    // RoPE on q and k
    {
        int tq = BATCH * NHEADS * SEQ * 32;
        rope_kernel<<<(tq + 255) / 256, 256>>>(q, cosT, sinT, BATCH * NHEADS);
        int tk = BATCH * NKV * SEQ * 32;
        rope_kernel<<<(tk + 255) / 256, 256>>>(k, cosT, sinT, BATCH * NKV);
    }

    // Tensor-core flash attention (register-fragment softmax)
    attn_tc_kernel<<<dim3(SEQ / 128, BATCH * NHEADS), 256, ATTN_SMEM_BYTES>>>(q, k, v, ctx);

    // Output projection + bias
    gemm_pipe_kernel<<<dim3(DOUT / BN, MROWS / BM), 256, GEMM_SMEM_BYTES>>>(
        ctx, wo, nullptr, nullptr, out, nullptr, nullptr, bo, 1);
}

// round 10
// speedup vs baseline: 2.9720x; 1.0171x over previous
#include <cuda_runtime.h>
#include <cuda_bf16.h>
#include <math.h>
#include <stdint.h>

// Problem constants
#define BATCH   2
#define SEQ     2048
#define DIN     2048
#define DOUT    2048
#define NHEADS  32
#define NKV     8
#define HD      64
#define MROWS   (BATCH * SEQ)      // 4096
#define NKVD    (NKV * HD)         // 512

// Scratch (allocation-free rule: __device__ globals)
__device__ float g_q[(size_t)BATCH * NHEADS * SEQ * HD];   // 32MB
__device__ float g_k[(size_t)BATCH * NKV * SEQ * HD];      //  8MB
__device__ float g_v[(size_t)BATCH * NKV * SEQ * HD];      //  8MB
__device__ float g_ctx[(size_t)MROWS * DOUT];              // 32MB (tf32-rounded)
__device__ float g_xr[(size_t)MROWS * DIN];                // 32MB x, tf32-rounded
__device__ float g_wqT[(size_t)DOUT * DIN];                // 16MB [N][K], rounded
__device__ float g_wkT[(size_t)NKVD * DIN];                //  4MB
__device__ float g_wvT[(size_t)NKVD * DIN];                //  4MB
__device__ float g_woT[(size_t)DOUT * DIN];                // 16MB

// ----------------------------------------------------------------------------
// Helpers
// ----------------------------------------------------------------------------
__device__ __forceinline__ float to_tf32(float x) {
    uint32_t u;
    asm("cvt.rna.tf32.f32 %0, %1;" : "=r"(u) : "f"(x));
    return __uint_as_float(u);
}

__device__ __forceinline__ void mma_tf32(float c[4],
                                         uint32_t a0, uint32_t a1, uint32_t a2, uint32_t a3,
                                         uint32_t b0, uint32_t b1) {
    asm volatile(
        "mma.sync.aligned.m16n8k8.row.col.f32.tf32.tf32.f32 "
        "{%0,%1,%2,%3}, {%4,%5,%6,%7}, {%8,%9}, {%0,%1,%2,%3};"
        : "+f"(c[0]), "+f"(c[1]), "+f"(c[2]), "+f"(c[3])
        : "r"(a0), "r"(a1), "r"(a2), "r"(a3), "r"(b0), "r"(b1));
}

__device__ __forceinline__ void ldsm_x4(uint32_t& r0, uint32_t& r1,
                                        uint32_t& r2, uint32_t& r3, uint32_t addr) {
    asm volatile("ldmatrix.sync.aligned.m8n8.x4.shared.b16 {%0,%1,%2,%3}, [%4];"
                 : "=r"(r0), "=r"(r1), "=r"(r2), "=r"(r3) : "r"(addr));
}

__device__ __forceinline__ void cp_async16(void* smem_dst, const void* gsrc) {
    uint32_t s = (uint32_t)__cvta_generic_to_shared(smem_dst);
    asm volatile("cp.async.cg.shared.global [%0], [%1], 16;\n" :: "r"(s), "l"(gsrc));
}
__device__ __forceinline__ void cp_commit() {
    asm volatile("cp.async.commit_group;\n");
}
template <int N>
__device__ __forceinline__ void cp_wait() {
    asm volatile("cp.async.wait_group %0;\n" :: "n"(N));
}

__device__ __forceinline__ uint32_t smem_u32(const void* p) {
    uint32_t a;
    asm("{ .reg .u64 t; cvta.to.shared.u64 t, %1; cvt.u32.u64 %0, t; }" : "=r"(a) : "l"(p));
    return a;
}

// ----------------------------------------------------------------------------
// Prep kernels: tf32-round x; transpose+round weights to [N][K]
// ----------------------------------------------------------------------------
__global__ void prep_roundx(const float* __restrict__ x, float* __restrict__ xr) {
    int i = blockIdx.x * blockDim.x + threadIdx.x;
    float4 v = *(const float4*)&x[(size_t)i * 4];
    v.x = to_tf32(v.x); v.y = to_tf32(v.y);
    v.z = to_tf32(v.z); v.w = to_tf32(v.w);
    *(float4*)&xr[(size_t)i * 4] = v;
}

__global__ void prep_transpose(const float* __restrict__ wq, const float* __restrict__ wk,
                               const float* __restrict__ wv, const float* __restrict__ wo,
                               float* __restrict__ wqT, float* __restrict__ wkT,
                               float* __restrict__ wvT, float* __restrict__ woT) {
    __shared__ float t[32][33];
    int bid = blockIdx.x;
    const float* src; float* dst; int cols, tb;
    if (bid < 4096)       { src = wq; dst = wqT; cols = 2048; tb = bid; }
    else if (bid < 5120)  { src = wk; dst = wkT; cols = 512;  tb = bid - 4096; }
    else if (bid < 6144)  { src = wv; dst = wvT; cols = 512;  tb = bid - 5120; }
    else                  { src = wo; dst = woT; cols = 2048; tb = bid - 6144; }
    int tpr = cols / 32;
    int k0 = (tb / tpr) * 32;
    int n0 = (tb % tpr) * 32;
    int lr = threadIdx.x >> 5, lc = threadIdx.x & 31;
#pragma unroll
    for (int i = 0; i < 4; i++) {
        int k = k0 + lr + i * 8;
        t[lr + i * 8][lc] = to_tf32(src[(size_t)k * cols + n0 + lc]);
    }
    __syncthreads();
#pragma unroll
    for (int i = 0; i < 4; i++) {
        int n = n0 + lr + i * 8;
        dst[(size_t)n * DIN + k0 + lc] = t[lc][lr + i * 8];
    }
}

// ----------------------------------------------------------------------------
// mma.sync tf32 GEMM with ldmatrix fragment loads.
// C[4096, N] = A[4096, 2048] * BT[N, 2048]^T    (A, BT pre-tf32-rounded)
// 128x128 tile, BK=16, 3-stage cp.async, 8 warps (2M x 4N), warp 64x32.
// Smem rows padded to 20 floats (80B) -> all LDSM phases conflict-free.
// mode 0: scatter to [b,h,s,d] (fused QKV). mode 1: row-major + bias.
// ----------------------------------------------------------------------------
#define ROWB 80                         // bytes per smem row (20 floats)
#define A_BYTES (128 * ROWB)            // 10240
#define STAGE_BYTES (2 * A_BYTES)       // 20480 (A then B)
#define GEMM_STAGES 3
#define GEMM_SMEM_BYTES (GEMM_STAGES * STAGE_BYTES)   // 61440

__global__ __launch_bounds__(256, 1)
void gemm_ls_kernel(const float* __restrict__ A,
                    const float* __restrict__ BT0, const float* __restrict__ BT1,
                    const float* __restrict__ BT2,
                    float* __restrict__ out0, float* __restrict__ out1,
                    float* __restrict__ out2,
                    const float* __restrict__ bias, int mode)
{
    extern __shared__ char smp[];
    const uint32_t smem_base = smem_u32(smp);

    const int tid  = threadIdx.x;
    const int wid  = tid >> 5;
    const int lane = tid & 31;
    const int g    = lane >> 2;
    const int t    = lane & 3;
    const int warp_m = wid & 1;
    const int warp_n = wid >> 1;

    const int row0  = blockIdx.y * 128;
    const int col0g = blockIdx.x * 128;

    const float* BT; float* outp; int Hh, coll;
    if (mode == 1 || col0g < DOUT)  { BT = BT0; outp = out0; Hh = NHEADS; coll = col0g; }
    else if (col0g < DOUT + NKVD)   { BT = BT1; outp = out1; Hh = NKV;    coll = col0g - DOUT; }
    else                            { BT = BT2; outp = out2; Hh = NKV;    coll = col0g - DOUT - NKVD; }

    // cp.async indexing: 512 16B-chunks per operand per BK=16 chunk, 2/thread
    const int ld_row = tid >> 2;       // + 64
    const int ld_c16 = tid & 3;

    auto issue_load = [&](int stage, int kc) {
        const int k0 = kc * 16;
        char* sA = smp + stage * STAGE_BYTES;
        char* sB = sA + A_BYTES;
#pragma unroll
        for (int r = 0; r < 2; r++) {
            int row = ld_row + r * 64;
            cp_async16(sA + row * ROWB + ld_c16 * 16,
                       &A[(size_t)(row0 + row) * DIN + k0 + ld_c16 * 4]);
            cp_async16(sB + row * ROWB + ld_c16 * 16,
                       &BT[(size_t)(coll + row) * DIN + k0 + ld_c16 * 4]);
        }
        cp_commit();
    };

    // Per-thread ldmatrix address offsets (bytes)
    // A x4: tiles {rows+0-7 col kb, rows+8-15 col kb, rows+0-7 col kb+4, rows+8-15 col kb+4}
    const uint32_t offA = (uint32_t)(((lane & 7) + ((lane >> 3) & 1) * 8 + warp_m * 64) * ROWB
                                     + (lane >> 4) * 16);
    // B x4: tiles {n+0-7 col kb, n+0-7 col kb+4, n+8-15 col kb, n+8-15 col kb+4}
    const uint32_t offB = (uint32_t)(((lane & 7) + ((lane >> 4) & 1) * 8 + warp_n * 32) * ROWB
                                     + ((lane >> 3) & 1) * 16);

    float c[4][4][4];
#pragma unroll
    for (int i = 0; i < 4; i++)
#pragma unroll
        for (int j = 0; j < 4; j++)
#pragma unroll
            for (int r = 0; r < 4; r++) c[i][j][r] = 0.f;

    issue_load(0, 0);
    issue_load(1, 1);

    const int NCHUNK = DIN / 16;   // 128
    int stage = 0;
    for (int kc = 0; kc < NCHUNK; kc++) {
        cp_wait<1>();
        __syncthreads();

        if (kc + 2 < NCHUNK) issue_load((stage + 2) % GEMM_STAGES, kc + 2);
        else cp_commit();

        const uint32_t sA = smem_base + stage * STAGE_BYTES;
        const uint32_t sB = sA + A_BYTES;

#pragma unroll
        for (int ks = 0; ks < 2; ks++) {
            const uint32_t kbb = ks * 32;   // kb*4 bytes
            uint32_t af[4][4];
#pragma unroll
            for (int mt = 0; mt < 4; mt++)
                ldsm_x4(af[mt][0], af[mt][1], af[mt][2], af[mt][3],
                        sA + offA + mt * (16 * ROWB) + kbb);
            uint32_t bf[4][2];
#pragma unroll
            for (int np = 0; np < 2; np++) {
                uint32_t r0, r1, r2, r3;
                ldsm_x4(r0, r1, r2, r3, sB + offB + np * (16 * ROWB) + kbb);
                bf[2 * np][0] = r0;  bf[2 * np][1] = r1;
                bf[2 * np + 1][0] = r2;  bf[2 * np + 1][1] = r3;
            }
#pragma unroll
            for (int mt = 0; mt < 4; mt++)
#pragma unroll
                for (int nt = 0; nt < 4; nt++)
                    mma_tf32(c[mt][nt], af[mt][0], af[mt][1], af[mt][2], af[mt][3],
                             bf[nt][0], bf[nt][1]);
        }

        __syncthreads();
        stage = (stage + 1) % GEMM_STAGES;
    }

    // Epilogue
#pragma unroll
    for (int mt = 0; mt < 4; mt++) {
        int rbase = row0 + warp_m * 64 + mt * 16;
#pragma unroll
        for (int nt = 0; nt < 4; nt++) {
            int cbase = coll + warp_n * 32 + nt * 8;
#pragma unroll
            for (int half = 0; half < 2; half++) {
                int r = rbase + g + half * 8;
                float v0 = c[mt][nt][half * 2 + 0];
                float v1 = c[mt][nt][half * 2 + 1];
                int n0 = cbase + t * 2;
                if (mode == 0) {
                    int b = r >> 11;
                    int s = r & 2047;
                    int h = n0 >> 6;
                    int d = n0 & 63;
                    float* p = &outp[(((size_t)(b * Hh + h)) * SEQ + s) * HD + d];
                    p[0] = v0;
                    p[1] = v1;   // d even, same head
                } else {
                    float2 o;
                    o.x = v0 + bias[n0];
                    o.y = v1 + bias[n0 + 1];
                    *(float2*)&outp[(size_t)r * DOUT + n0] = o;
                }
            }
        }
    }
}

// ----------------------------------------------------------------------------
// RoPE (in-place on [BH, S, 64])
// ----------------------------------------------------------------------------
__global__ void rope_kernel(float* __restrict__ buf,
                            const float* __restrict__ cosT,
                            const float* __restrict__ sinT, int BH)
{
    int idx = blockIdx.x * blockDim.x + threadIdx.x;
    int total = BH * SEQ * 32;
    if (idx >= total) return;
    int d  = idx & 31;
    int s  = (idx >> 5) & (SEQ - 1);
    int bh = idx >> 16;
    float* p = buf + ((size_t)bh * SEQ + s) * HD;
    float t1 = p[d];
    float t2 = p[d + 32];
    float cv = cosT[s * HD + d];
    float sv = sinT[s * HD + d];
    p[d]      = t1 * cv - t2 * sv;
    p[d + 32] = t2 * cv + t1 * sv;
}

// ----------------------------------------------------------------------------
// Tensor-core flash attention (round 8, + tf32-rounded ctx output so the
// out-proj GEMM can consume A without per-fragment cvt)
// ----------------------------------------------------------------------------
#define QPAD 68

__global__ __launch_bounds__(256, 2)
void attn_tc_kernel(const float* __restrict__ q, const float* __restrict__ k,
                    const float* __restrict__ v, float* __restrict__ ctx)
{
    extern __shared__ float sm[];
    float* Qs = sm;
    float* Ps = Qs + 128 * QPAD;
    float* Ks = Ps + 128 * QPAD;
    float* Vs = Ks + 64 * QPAD;

    const int tid  = threadIdx.x;
    const int wid  = tid >> 5;
    const int lane = tid & 31;
    const int g    = lane >> 2;
    const int t    = lane & 3;

    const int bh = blockIdx.y;
    const int b  = bh >> 5;
    const int h  = bh & 31;
    const int kvg = h >> 2;
    const int qi0 = blockIdx.x * 128;
    const int mb  = wid * 16;

    const float* Q = q + ((size_t)(b * NHEADS + h)  * SEQ) * HD;
    const float* K = k + ((size_t)(b * NKV + kvg)   * SEQ) * HD;
    const float* V = v + ((size_t)(b * NKV + kvg)   * SEQ) * HD;

#pragma unroll
    for (int r = 0; r < 8; r++) {
        int idx = tid + r * 256;
        int qr = idx >> 4;
        int c4 = idx & 15;
        float4 vv = *(const float4*)&Q[(size_t)(qi0 + qr) * HD + c4 * 4];
        vv.x = to_tf32(vv.x); vv.y = to_tf32(vv.y);
        vv.z = to_tf32(vv.z); vv.w = to_tf32(vv.w);
        *(float4*)&Qs[qr * QPAD + c4 * 4] = vv;
    }

    const int row0g = qi0 + mb + g;
    const int row1g = row0g + 8;
    float mi0 = -INFINITY, mi1 = -INFINITY;
    float li0 = 0.f, li1 = 0.f;

    float o[8][4];
#pragma unroll
    for (int n = 0; n < 8; n++)
#pragma unroll
        for (int r = 0; r < 4; r++) o[n][r] = 0.f;

    const int ntiles = 2 * blockIdx.x + 2;
    const float scale = 0.125f;

    for (int tt = 0; tt < ntiles; tt++) {
        const int kj0 = tt * 64;
        __syncthreads();

#pragma unroll
        for (int r = 0; r < 4; r++) {
            int idx = tid + r * 256;
            int kr = idx >> 4;
            int c4 = idx & 15;
            float4 a = *(const float4*)&K[(size_t)(kj0 + kr) * HD + c4 * 4];
            a.x = to_tf32(a.x); a.y = to_tf32(a.y);
            a.z = to_tf32(a.z); a.w = to_tf32(a.w);
            *(float4*)&Ks[kr * QPAD + c4 * 4] = a;
            float4 bb = *(const float4*)&V[(size_t)(kj0 + kr) * HD + c4 * 4];
            bb.x = to_tf32(bb.x); bb.y = to_tf32(bb.y);
            bb.z = to_tf32(bb.z); bb.w = to_tf32(bb.w);
            *(float4*)&Vs[kr * QPAD + c4 * 4] = bb;
        }
        __syncthreads();

        float sfr[8][4];
#pragma unroll
        for (int n = 0; n < 8; n++)
#pragma unroll
            for (int r = 0; r < 4; r++) sfr[n][r] = 0.f;

#pragma unroll
        for (int kk = 0; kk < 8; kk++) {
            const int kb = kk * 8;
            uint32_t a0 = __float_as_uint(Qs[(mb + g    ) * QPAD + kb + t    ]);
            uint32_t a1 = __float_as_uint(Qs[(mb + g + 8) * QPAD + kb + t    ]);
            uint32_t a2 = __float_as_uint(Qs[(mb + g    ) * QPAD + kb + t + 4]);
            uint32_t a3 = __float_as_uint(Qs[(mb + g + 8) * QPAD + kb + t + 4]);
#pragma unroll
            for (int n = 0; n < 8; n++) {
                const int nb = n * 8;
                uint32_t b0 = __float_as_uint(Ks[(nb + g) * QPAD + kb + t    ]);
                uint32_t b1 = __float_as_uint(Ks[(nb + g) * QPAD + kb + t + 4]);
                mma_tf32(sfr[n], a0, a1, a2, a3, b0, b1);
            }
        }

        float rm0 = -INFINITY, rm1 = -INFINITY;
#pragma unroll
        for (int n = 0; n < 8; n++) {
            const int c0 = kj0 + n * 8 + 2 * t;
            const int c1 = c0 + 1;
            sfr[n][0] = (c0 <= row0g) ? sfr[n][0] * scale : -INFINITY;
            sfr[n][1] = (c1 <= row0g) ? sfr[n][1] * scale : -INFINITY;
            sfr[n][2] = (c0 <= row1g) ? sfr[n][2] * scale : -INFINITY;
            sfr[n][3] = (c1 <= row1g) ? sfr[n][3] * scale : -INFINITY;
            rm0 = fmaxf(rm0, fmaxf(sfr[n][0], sfr[n][1]));
            rm1 = fmaxf(rm1, fmaxf(sfr[n][2], sfr[n][3]));
        }
        rm0 = fmaxf(rm0, __shfl_xor_sync(0xffffffffu, rm0, 1));
        rm0 = fmaxf(rm0, __shfl_xor_sync(0xffffffffu, rm0, 2));
        rm1 = fmaxf(rm1, __shfl_xor_sync(0xffffffffu, rm1, 1));
        rm1 = fmaxf(rm1, __shfl_xor_sync(0xffffffffu, rm1, 2));

        const float nm0 = fmaxf(mi0, rm0);
        const float nm1 = fmaxf(mi1, rm1);
        const float al0 = __expf(mi0 - nm0);
        const float al1 = __expf(mi1 - nm1);

        float s0 = 0.f, s1 = 0.f;
#pragma unroll
        for (int n = 0; n < 8; n++) {
            float p0 = __expf(sfr[n][0] - nm0);
            float p1 = __expf(sfr[n][1] - nm0);
            float p2 = __expf(sfr[n][2] - nm1);
            float p3 = __expf(sfr[n][3] - nm1);
            s0 += p0 + p1;
            s1 += p2 + p3;
            sfr[n][0] = to_tf32(p0);
            sfr[n][1] = to_tf32(p1);
            sfr[n][2] = to_tf32(p2);
            sfr[n][3] = to_tf32(p3);
        }
        s0 += __shfl_xor_sync(0xffffffffu, s0, 1);
        s0 += __shfl_xor_sync(0xffffffffu, s0, 2);
        s1 += __shfl_xor_sync(0xffffffffu, s1, 1);
        s1 += __shfl_xor_sync(0xffffffffu, s1, 2);

        li0 = li0 * al0 + s0;  mi0 = nm0;
        li1 = li1 * al1 + s1;  mi1 = nm1;

#pragma unroll
        for (int n = 0; n < 8; n++) {
            o[n][0] *= al0; o[n][1] *= al0;
            o[n][2] *= al1; o[n][3] *= al1;
        }

#pragma unroll
        for (int n = 0; n < 8; n++) {
            const int nb = n * 8;
            *(float2*)&Ps[(mb + g    ) * QPAD + nb + 2 * t] = make_float2(sfr[n][0], sfr[n][1]);
            *(float2*)&Ps[(mb + g + 8) * QPAD + nb + 2 * t] = make_float2(sfr[n][2], sfr[n][3]);
        }
        __syncwarp();

#pragma unroll
        for (int kk = 0; kk < 8; kk++) {
            const int kb = kk * 8;
            uint32_t a0 = __float_as_uint(Ps[(mb + g    ) * QPAD + kb + t    ]);
            uint32_t a1 = __float_as_uint(Ps[(mb + g + 8) * QPAD + kb + t    ]);
            uint32_t a2 = __float_as_uint(Ps[(mb + g    ) * QPAD + kb + t + 4]);
            uint32_t a3 = __float_as_uint(Ps[(mb + g + 8) * QPAD + kb + t + 4]);
#pragma unroll
            for (int n = 0; n < 8; n++) {
                const int nb = n * 8;
                uint32_t b0 = __float_as_uint(Vs[(kb + t    ) * QPAD + nb + g]);
                uint32_t b1 = __float_as_uint(Vs[(kb + t + 4) * QPAD + nb + g]);
                mma_tf32(o[n], a0, a1, a2, a3, b0, b1);
            }
        }
    }

    // Epilogue: normalize, tf32-round, write ctx [b*s, h*64+d]
    {
        const float inv0 = 1.0f / li0;
        const float inv1 = 1.0f / li1;
#pragma unroll
        for (int n = 0; n < 8; n++) {
            int col = h * HD + n * 8 + 2 * t;
            float2 v0 = make_float2(to_tf32(o[n][0] * inv0), to_tf32(o[n][1] * inv0));
            float2 v1 = make_float2(to_tf32(o[n][2] * inv1), to_tf32(o[n][3] * inv1));
            *(float2*)&ctx[((size_t)(b * SEQ + row0g)) * DOUT + col] = v0;
            *(float2*)&ctx[((size_t)(b * SEQ + row1g)) * DOUT + col] = v1;
        }
    }
}

// ----------------------------------------------------------------------------
// Launch.  Inputs: 0:x 1:mask 2:cos 3:sin 4:wq 5:wk 6:wv 7:wo 8:bo
// ----------------------------------------------------------------------------
#define ATTN_SMEM_BYTES ((384 * QPAD) * 4)

extern "C" void kernel_launch(void* const* d_in, const int* in_sizes, int n_in,
                              void* d_out, int out_size)
{
    const float* x    = (const float*)d_in[0];
    const float* cosT = (const float*)d_in[2];
    const float* sinT = (const float*)d_in[3];
    const float* wq   = (const float*)d_in[4];
    const float* wk   = (const float*)d_in[5];
    const float* wv   = (const float*)d_in[6];
    const float* wo   = (const float*)d_in[7];
    const float* bo   = (const float*)d_in[8];
    float* out = (float*)d_out;

    float *q, *k, *v, *ctx, *xr, *wqT, *wkT, *wvT, *woT;
    cudaGetSymbolAddress((void**)&q,   g_q);
    cudaGetSymbolAddress((void**)&k,   g_k);
    cudaGetSymbolAddress((void**)&v,   g_v);
    cudaGetSymbolAddress((void**)&ctx, g_ctx);
    cudaGetSymbolAddress((void**)&xr,  g_xr);
    cudaGetSymbolAddress((void**)&wqT, g_wqT);
    cudaGetSymbolAddress((void**)&wkT, g_wkT);
    cudaGetSymbolAddress((void**)&wvT, g_wvT);
    cudaGetSymbolAddress((void**)&woT, g_woT);

    cudaFuncSetAttribute(gemm_ls_kernel,
                         cudaFuncAttributeMaxDynamicSharedMemorySize, GEMM_SMEM_BYTES);
    cudaFuncSetAttribute(attn_tc_kernel,
                         cudaFuncAttributeMaxDynamicSharedMemorySize, ATTN_SMEM_BYTES);

    // Prep: tf32-round x; transpose+round weights to [N][K]
    prep_roundx<<<(MROWS * DIN / 4) / 256, 256>>>(x, xr);
    prep_transpose<<<10240, 256>>>(wq, wk, wv, wo, wqT, wkT, wvT, woT);

    // Fused QKV projection (ldmatrix mma.sync)
    gemm_ls_kernel<<<dim3((DOUT + 2 * NKVD) / 128, MROWS / 128), 256, GEMM_SMEM_BYTES>>>(
        xr, wqT, wkT, wvT, q, k, v, nullptr, 0);

    // RoPE on q and k
    {
        int tq = BATCH * NHEADS * SEQ * 32;
        rope_kernel<<<(tq + 255) / 256, 256>>>(q, cosT, sinT, BATCH * NHEADS);
        int tk = BATCH * NKV * SEQ * 32;
        rope_kernel<<<(tk + 255) / 256, 256>>>(k, cosT, sinT, BATCH * NKV);
    }

    // Tensor-core flash attention
    attn_tc_kernel<<<dim3(SEQ / 128, BATCH * NHEADS), 256, ATTN_SMEM_BYTES>>>(q, k, v, ctx);

    // Output projection + bias (ldmatrix mma.sync)
    gemm_ls_kernel<<<dim3(DOUT / 128, MROWS / 128), 256, GEMM_SMEM_BYTES>>>(
        ctx, woT, nullptr, nullptr, out, nullptr, nullptr, bo, 1);
}

// round 11
// speedup vs baseline: 3.4063x; 1.1461x over previous
#include <cuda_runtime.h>
#include <cuda_bf16.h>
#include <math.h>
#include <stdint.h>

// Problem constants
#define BATCH   2
#define SEQ     2048
#define DIN     2048
#define DOUT    2048
#define NHEADS  32
#define NKV     8
#define HD      64
#define MROWS   (BATCH * SEQ)      // 4096
#define NKVD    (NKV * HD)         // 512

// Scratch (allocation-free rule: __device__ globals)
__device__ float g_q[(size_t)BATCH * NHEADS * SEQ * HD];   // 32MB
__device__ float g_k[(size_t)BATCH * NKV * SEQ * HD];      //  8MB
__device__ float g_v[(size_t)BATCH * NKV * SEQ * HD];      //  8MB
__device__ float g_ctx[(size_t)MROWS * DOUT];              // 32MB (tf32-rounded)
__device__ float g_xr[(size_t)MROWS * DIN];                // 32MB x, tf32-rounded
__device__ float g_wqT[(size_t)DOUT * DIN];                // 16MB [N][K], rounded
__device__ float g_wkT[(size_t)NKVD * DIN];                //  4MB
__device__ float g_wvT[(size_t)NKVD * DIN];                //  4MB
__device__ float g_woT[(size_t)DOUT * DIN];                // 16MB

// ----------------------------------------------------------------------------
// Helpers
// ----------------------------------------------------------------------------
__device__ __forceinline__ float to_tf32(float x) {
    uint32_t u;
    asm("cvt.rna.tf32.f32 %0, %1;" : "=r"(u) : "f"(x));
    return __uint_as_float(u);
}

__device__ __forceinline__ void mma_tf32(float c[4],
                                         uint32_t a0, uint32_t a1, uint32_t a2, uint32_t a3,
                                         uint32_t b0, uint32_t b1) {
    asm volatile(
        "mma.sync.aligned.m16n8k8.row.col.f32.tf32.tf32.f32 "
        "{%0,%1,%2,%3}, {%4,%5,%6,%7}, {%8,%9}, {%0,%1,%2,%3};"
        : "+f"(c[0]), "+f"(c[1]), "+f"(c[2]), "+f"(c[3])
        : "r"(a0), "r"(a1), "r"(a2), "r"(a3), "r"(b0), "r"(b1));
}

__device__ __forceinline__ void ldsm_x4(uint32_t& r0, uint32_t& r1,
                                        uint32_t& r2, uint32_t& r3, uint32_t addr) {
    asm volatile("ldmatrix.sync.aligned.m8n8.x4.shared.b16 {%0,%1,%2,%3}, [%4];"
                 : "=r"(r0), "=r"(r1), "=r"(r2), "=r"(r3) : "r"(addr));
}

__device__ __forceinline__ uint32_t smem_u32(const void* p) {
    uint32_t a;
    asm("{ .reg .u64 t; cvta.to.shared.u64 t, %1; cvt.u32.u64 %0, t; }" : "=r"(a) : "l"(p));
    return a;
}

#define MBARRIER_INIT(addr, cnt) \
    asm volatile("mbarrier.init.shared.b64 [%0], %1;" :: "r"(addr), "r"(cnt) : "memory")

__device__ __forceinline__ void mbar_expect_tx(uint32_t mbar, uint32_t bytes) {
    asm volatile("mbarrier.arrive.expect_tx.shared.b64 _, [%0], %1;"
                 :: "r"(mbar), "r"(bytes) : "memory");
}

__device__ __forceinline__ void mbar_wait_parity(uint32_t mbar, uint32_t parity) {
    uint32_t done;
    asm volatile(
        "{\n\t.reg .pred p;\n\t"
        "mbarrier.try_wait.parity.shared.b64 p, [%1], %2;\n\t"
        "selp.b32 %0, 1, 0, p;\n\t}"
        : "=r"(done) : "r"(mbar), "r"(parity) : "memory");
    if (!done) {
        asm volatile(
            "{\n\t.reg .pred P1;\n\t"
            "WL_%=:\n\t"
            "mbarrier.try_wait.parity.shared.b64 P1, [%0], %1;\n\t"
            "@P1 bra.uni WD_%=;\n\t"
            "bra.uni WL_%=;\n\t"
            "WD_%=:\n\t}"
            :: "r"(mbar), "r"(parity) : "memory");
    }
}

__device__ __forceinline__ void bulk_g2s(uint32_t dst, const void* src,
                                         uint32_t bytes, uint32_t mbar) {
    asm volatile(
        "cp.async.bulk.shared::cluster.global.mbarrier::complete_tx::bytes "
        "[%0], [%1], %2, [%3];"
        :: "r"(dst), "l"(src), "r"(bytes), "r"(mbar) : "memory");
}

// ----------------------------------------------------------------------------
// Prep kernels: tf32-round x; transpose+round weights to [N][K]
// ----------------------------------------------------------------------------
__global__ void prep_roundx(const float* __restrict__ x, float* __restrict__ xr) {
    int i = blockIdx.x * blockDim.x + threadIdx.x;
    float4 v = *(const float4*)&x[(size_t)i * 4];
    v.x = to_tf32(v.x); v.y = to_tf32(v.y);
    v.z = to_tf32(v.z); v.w = to_tf32(v.w);
    *(float4*)&xr[(size_t)i * 4] = v;
}

__global__ void prep_transpose(const float* __restrict__ wq, const float* __restrict__ wk,
                               const float* __restrict__ wv, const float* __restrict__ wo,
                               float* __restrict__ wqT, float* __restrict__ wkT,
                               float* __restrict__ wvT, float* __restrict__ woT) {
    __shared__ float t[32][33];
    int bid = blockIdx.x;
    const float* src; float* dst; int cols, tb;
    if (bid < 4096)       { src = wq; dst = wqT; cols = 2048; tb = bid; }
    else if (bid < 5120)  { src = wk; dst = wkT; cols = 512;  tb = bid - 4096; }
    else if (bid < 6144)  { src = wv; dst = wvT; cols = 512;  tb = bid - 5120; }
    else                  { src = wo; dst = woT; cols = 2048; tb = bid - 6144; }
    int tpr = cols / 32;
    int k0 = (tb / tpr) * 32;
    int n0 = (tb % tpr) * 32;
    int lr = threadIdx.x >> 5, lc = threadIdx.x & 31;
#pragma unroll
    for (int i = 0; i < 4; i++) {
        int k = k0 + lr + i * 8;
        t[lr + i * 8][lc] = to_tf32(src[(size_t)k * cols + n0 + lc]);
    }
    __syncthreads();
#pragma unroll
    for (int i = 0; i < 4; i++) {
        int n = n0 + lr + i * 8;
        dst[(size_t)n * DIN + k0 + lc] = t[lc][lr + i * 8];
    }
}

// ----------------------------------------------------------------------------
// mma.sync tf32 GEMM, cp.async.bulk staging + ldmatrix fragments.
// C[4096, N] = A[4096, 2048] * BT[N, 2048]^T   (A, BT pre-tf32-rounded)
// 128x128 tile, BK=32 floats (one 128B bulk per row), 3-stage mbarrier
// pipeline, 8 warps (2M x 4N), warp tile 64x32.
// Smem row stride 144B: 16B-aligned for bulk, conflict-free for LDSM.
// mode 0: scatter to [b,h,s,d] (fused QKV). mode 1: row-major + bias.
// ----------------------------------------------------------------------------
#define GBK 32
#define GROWB 144                        // bytes per smem row (36 floats)
#define G_A_BYTES (128 * GROWB)          // 18,432
#define G_STAGE (2 * G_A_BYTES)          // 36,864
#define G_STAGES 3
#define G_STAGE_TX 32768u                // 256 rows * 128B
#define GEMM_SMEM (G_STAGES * G_STAGE + 64)   // + mbarriers

__global__ __launch_bounds__(256, 2)
void gemm_blk_kernel(const float* __restrict__ A,
                     const float* __restrict__ BT0, const float* __restrict__ BT1,
                     const float* __restrict__ BT2,
                     float* __restrict__ out0, float* __restrict__ out1,
                     float* __restrict__ out2,
                     const float* __restrict__ bias, int mode)
{
    extern __shared__ char smp[];
    const uint32_t sbase = smem_u32(smp);
    const uint32_t mbar0 = sbase + G_STAGES * G_STAGE;   // 3 x 8B

    const int tid  = threadIdx.x;
    const int wid  = tid >> 5;
    const int lane = tid & 31;
    const int g    = lane >> 2;
    const int t    = lane & 3;
    const int warp_m = wid & 1;
    const int warp_n = wid >> 1;

    const int row0  = blockIdx.y * 128;
    const int col0g = blockIdx.x * 128;

    const float* BT; float* outp; int Hh, coll;
    if (mode == 1 || col0g < DOUT)  { BT = BT0; outp = out0; Hh = NHEADS; coll = col0g; }
    else if (col0g < DOUT + NKVD)   { BT = BT1; outp = out1; Hh = NKV;    coll = col0g - DOUT; }
    else                            { BT = BT2; outp = out2; Hh = NKV;    coll = col0g - DOUT - NKVD; }

    if (tid == 0) {
#pragma unroll
        for (int s = 0; s < G_STAGES; s++) MBARRIER_INIT(mbar0 + s * 8, 1);
    }
    __syncthreads();

    // Bulk staging: thread i -> one 128B row-chunk (i<128: A row i; else B row i-128)
    const int brow = tid & 127;
    const float* gsrcA = &A [(size_t)(row0 + brow) * DIN];
    const float* gsrcB = &BT[(size_t)(coll + brow) * DIN];
    const float* gsrc  = (tid < 128) ? gsrcA : gsrcB;
    const uint32_t dst_off = (tid < 128 ? 0u : (uint32_t)G_A_BYTES) + (uint32_t)brow * GROWB;

    auto issue_bulk = [&](int stage, int kc) {
        bulk_g2s(sbase + stage * G_STAGE + dst_off, gsrc + kc * GBK, 128u,
                 mbar0 + stage * 8);
    };

    // ldmatrix per-thread offsets (bytes)
    const uint32_t offA = (uint32_t)(((lane & 7) + ((lane >> 3) & 1) * 8 + warp_m * 64) * GROWB
                                     + (lane >> 4) * 16);
    const uint32_t offB = (uint32_t)(((lane & 7) + ((lane >> 4) & 1) * 8 + warp_n * 32) * GROWB
                                     + ((lane >> 3) & 1) * 16);

    float c[4][4][4];
#pragma unroll
    for (int i = 0; i < 4; i++)
#pragma unroll
        for (int j = 0; j < 4; j++)
#pragma unroll
            for (int r = 0; r < 4; r++) c[i][j][r] = 0.f;

    // Prologue: fill stages 0,1
    if (tid == 0) {
        mbar_expect_tx(mbar0 + 0, G_STAGE_TX);
        mbar_expect_tx(mbar0 + 8, G_STAGE_TX);
    }
    issue_bulk(0, 0);
    issue_bulk(1, 1);

    const int NCH = DIN / GBK;   // 64
    for (int kc = 0; kc < NCH; kc++) {
        const int s = kc % 3;
        const uint32_t par = (uint32_t)((kc / 3) & 1);
        mbar_wait_parity(mbar0 + s * 8, par);
        __syncthreads();   // all warps past previous iter's reads of stage s2

        if (kc + 2 < NCH) {
            const int s2 = (kc + 2) % 3;
            if (tid == 0) mbar_expect_tx(mbar0 + s2 * 8, G_STAGE_TX);
            issue_bulk(s2, kc + 2);
        }

        const uint32_t sA = sbase + s * G_STAGE;
        const uint32_t sB = sA + G_A_BYTES;

#pragma unroll
        for (int ks = 0; ks < 4; ks++) {
            const uint32_t kbb = ks * 32;
            uint32_t af[4][4];
#pragma unroll
            for (int mt = 0; mt < 4; mt++)
                ldsm_x4(af[mt][0], af[mt][1], af[mt][2], af[mt][3],
                        sA + offA + mt * (16 * GROWB) + kbb);
            uint32_t bf[4][2];
#pragma unroll
            for (int np = 0; np < 2; np++) {
                uint32_t r0, r1, r2, r3;
                ldsm_x4(r0, r1, r2, r3, sB + offB + np * (16 * GROWB) + kbb);
                bf[2 * np][0] = r0;      bf[2 * np][1] = r1;
                bf[2 * np + 1][0] = r2;  bf[2 * np + 1][1] = r3;
            }
#pragma unroll
            for (int mt = 0; mt < 4; mt++)
#pragma unroll
                for (int nt = 0; nt < 4; nt++)
                    mma_tf32(c[mt][nt], af[mt][0], af[mt][1], af[mt][2], af[mt][3],
                             bf[nt][0], bf[nt][1]);
        }
    }

    // Epilogue
#pragma unroll
    for (int mt = 0; mt < 4; mt++) {
        int rbase = row0 + warp_m * 64 + mt * 16;
#pragma unroll
        for (int nt = 0; nt < 4; nt++) {
            int cbase = coll + warp_n * 32 + nt * 8;
#pragma unroll
            for (int half = 0; half < 2; half++) {
                int r = rbase + g + half * 8;
                float v0 = c[mt][nt][half * 2 + 0];
                float v1 = c[mt][nt][half * 2 + 1];
                int n0 = cbase + t * 2;
                if (mode == 0) {
                    int b = r >> 11;
                    int s = r & 2047;
                    int h = n0 >> 6;
                    int d = n0 & 63;
                    float* p = &outp[(((size_t)(b * Hh + h)) * SEQ + s) * HD + d];
                    p[0] = v0;
                    p[1] = v1;   // d even, same head
                } else {
                    float2 o;
                    o.x = v0 + bias[n0];
                    o.y = v1 + bias[n0 + 1];
                    *(float2*)&outp[(size_t)r * DOUT + n0] = o;
                }
            }
        }
    }
}

// ----------------------------------------------------------------------------
// RoPE, single launch over q (bh 0..63) and k (bh 64..79)
// ----------------------------------------------------------------------------
__global__ void rope_all_kernel(float* __restrict__ qb, float* __restrict__ kb,
                                const float* __restrict__ cosT,
                                const float* __restrict__ sinT)
{
    int idx = blockIdx.x * blockDim.x + threadIdx.x;   // < 80*2048*32
    int d  = idx & 31;
    int s  = (idx >> 5) & (SEQ - 1);
    int bh = idx >> 16;
    float* p = (bh < 64) ? qb + ((size_t)bh * SEQ + s) * HD
                         : kb + ((size_t)(bh - 64) * SEQ + s) * HD;
    float t1 = p[d];
    float t2 = p[d + 32];
    float cv = cosT[s * HD + d];
    float sv = sinT[s * HD + d];
    p[d]      = t1 * cv - t2 * sv;
    p[d + 32] = t2 * cv + t1 * sv;
}

// ----------------------------------------------------------------------------
// Tensor-core flash attention (unchanged — passing, 469us)
// ----------------------------------------------------------------------------
#define QPAD 68

__global__ __launch_bounds__(256, 2)
void attn_tc_kernel(const float* __restrict__ q, const float* __restrict__ k,
                    const float* __restrict__ v, float* __restrict__ ctx)
{
    extern __shared__ float sm[];
    float* Qs = sm;
    float* Ps = Qs + 128 * QPAD;
    float* Ks = Ps + 128 * QPAD;
    float* Vs = Ks + 64 * QPAD;

    const int tid  = threadIdx.x;
    const int wid  = tid >> 5;
    const int lane = tid & 31;
    const int g    = lane >> 2;
    const int t    = lane & 3;

    const int bh = blockIdx.y;
    const int b  = bh >> 5;
    const int h  = bh & 31;
    const int kvg = h >> 2;
    const int qi0 = blockIdx.x * 128;
    const int mb  = wid * 16;

    const float* Q = q + ((size_t)(b * NHEADS + h)  * SEQ) * HD;
    const float* K = k + ((size_t)(b * NKV + kvg)   * SEQ) * HD;
    const float* V = v + ((size_t)(b * NKV + kvg)   * SEQ) * HD;

#pragma unroll
    for (int r = 0; r < 8; r++) {
        int idx = tid + r * 256;
        int qr = idx >> 4;
        int c4 = idx & 15;
        float4 vv = *(const float4*)&Q[(size_t)(qi0 + qr) * HD + c4 * 4];
        vv.x = to_tf32(vv.x); vv.y = to_tf32(vv.y);
        vv.z = to_tf32(vv.z); vv.w = to_tf32(vv.w);
        *(float4*)&Qs[qr * QPAD + c4 * 4] = vv;
    }

    const int row0g = qi0 + mb + g;
    const int row1g = row0g + 8;
    float mi0 = -INFINITY, mi1 = -INFINITY;
    float li0 = 0.f, li1 = 0.f;

    float o[8][4];
#pragma unroll
    for (int n = 0; n < 8; n++)
#pragma unroll
        for (int r = 0; r < 4; r++) o[n][r] = 0.f;

    const int ntiles = 2 * blockIdx.x + 2;
    const float scale = 0.125f;

    for (int tt = 0; tt < ntiles; tt++) {
        const int kj0 = tt * 64;
        __syncthreads();

#pragma unroll
        for (int r = 0; r < 4; r++) {
            int idx = tid + r * 256;
            int kr = idx >> 4;
            int c4 = idx & 15;
            float4 a = *(const float4*)&K[(size_t)(kj0 + kr) * HD + c4 * 4];
            a.x = to_tf32(a.x); a.y = to_tf32(a.y);
            a.z = to_tf32(a.z); a.w = to_tf32(a.w);
            *(float4*)&Ks[kr * QPAD + c4 * 4] = a;
            float4 bb = *(const float4*)&V[(size_t)(kj0 + kr) * HD + c4 * 4];
            bb.x = to_tf32(bb.x); bb.y = to_tf32(bb.y);
            bb.z = to_tf32(bb.z); bb.w = to_tf32(bb.w);
            *(float4*)&Vs[kr * QPAD + c4 * 4] = bb;
        }
        __syncthreads();

        float sfr[8][4];
#pragma unroll
        for (int n = 0; n < 8; n++)
#pragma unroll
            for (int r = 0; r < 4; r++) sfr[n][r] = 0.f;

#pragma unroll
        for (int kk = 0; kk < 8; kk++) {
            const int kb = kk * 8;
            uint32_t a0 = __float_as_uint(Qs[(mb + g    ) * QPAD + kb + t    ]);
            uint32_t a1 = __float_as_uint(Qs[(mb + g + 8) * QPAD + kb + t    ]);
            uint32_t a2 = __float_as_uint(Qs[(mb + g    ) * QPAD + kb + t + 4]);
            uint32_t a3 = __float_as_uint(Qs[(mb + g + 8) * QPAD + kb + t + 4]);
#pragma unroll
            for (int n = 0; n < 8; n++) {
                const int nb = n * 8;
                uint32_t b0 = __float_as_uint(Ks[(nb + g) * QPAD + kb + t    ]);
                uint32_t b1 = __float_as_uint(Ks[(nb + g) * QPAD + kb + t + 4]);
                mma_tf32(sfr[n], a0, a1, a2, a3, b0, b1);
            }
        }

        float rm0 = -INFINITY, rm1 = -INFINITY;
#pragma unroll
        for (int n = 0; n < 8; n++) {
            const int c0 = kj0 + n * 8 + 2 * t;
            const int c1 = c0 + 1;
            sfr[n][0] = (c0 <= row0g) ? sfr[n][0] * scale : -INFINITY;
            sfr[n][1] = (c1 <= row0g) ? sfr[n][1] * scale : -INFINITY;
            sfr[n][2] = (c0 <= row1g) ? sfr[n][2] * scale : -INFINITY;
            sfr[n][3] = (c1 <= row1g) ? sfr[n][3] * scale : -INFINITY;
            rm0 = fmaxf(rm0, fmaxf(sfr[n][0], sfr[n][1]));
            rm1 = fmaxf(rm1, fmaxf(sfr[n][2], sfr[n][3]));
        }
        rm0 = fmaxf(rm0, __shfl_xor_sync(0xffffffffu, rm0, 1));
        rm0 = fmaxf(rm0, __shfl_xor_sync(0xffffffffu, rm0, 2));
        rm1 = fmaxf(rm1, __shfl_xor_sync(0xffffffffu, rm1, 1));
        rm1 = fmaxf(rm1, __shfl_xor_sync(0xffffffffu, rm1, 2));

        const float nm0 = fmaxf(mi0, rm0);
        const float nm1 = fmaxf(mi1, rm1);
        const float al0 = __expf(mi0 - nm0);
        const float al1 = __expf(mi1 - nm1);

        float s0 = 0.f, s1 = 0.f;
#pragma unroll
        for (int n = 0; n < 8; n++) {
            float p0 = __expf(sfr[n][0] - nm0);
            float p1 = __expf(sfr[n][1] - nm0);
            float p2 = __expf(sfr[n][2] - nm1);
            float p3 = __expf(sfr[n][3] - nm1);
            s0 += p0 + p1;
            s1 += p2 + p3;
            sfr[n][0] = to_tf32(p0);
            sfr[n][1] = to_tf32(p1);
            sfr[n][2] = to_tf32(p2);
            sfr[n][3] = to_tf32(p3);
        }
        s0 += __shfl_xor_sync(0xffffffffu, s0, 1);
        s0 += __shfl_xor_sync(0xffffffffu, s0, 2);
        s1 += __shfl_xor_sync(0xffffffffu, s1, 1);
        s1 += __shfl_xor_sync(0xffffffffu, s1, 2);

        li0 = li0 * al0 + s0;  mi0 = nm0;
        li1 = li1 * al1 + s1;  mi1 = nm1;

#pragma unroll
        for (int n = 0; n < 8; n++) {
            o[n][0] *= al0; o[n][1] *= al0;
            o[n][2] *= al1; o[n][3] *= al1;
        }

#pragma unroll
        for (int n = 0; n < 8; n++) {
            const int nb = n * 8;
            *(float2*)&Ps[(mb + g    ) * QPAD + nb + 2 * t] = make_float2(sfr[n][0], sfr[n][1]);
            *(float2*)&Ps[(mb + g + 8) * QPAD + nb + 2 * t] = make_float2(sfr[n][2], sfr[n][3]);
        }
        __syncwarp();

#pragma unroll
        for (int kk = 0; kk < 8; kk++) {
            const int kb = kk * 8;
            uint32_t a0 = __float_as_uint(Ps[(mb + g    ) * QPAD + kb + t    ]);
            uint32_t a1 = __float_as_uint(Ps[(mb + g + 8) * QPAD + kb + t    ]);
            uint32_t a2 = __float_as_uint(Ps[(mb + g    ) * QPAD + kb + t + 4]);
            uint32_t a3 = __float_as_uint(Ps[(mb + g + 8) * QPAD + kb + t + 4]);
#pragma unroll
            for (int n = 0; n < 8; n++) {
                const int nb = n * 8;
                uint32_t b0 = __float_as_uint(Vs[(kb + t    ) * QPAD + nb + g]);
                uint32_t b1 = __float_as_uint(Vs[(kb + t + 4) * QPAD + nb + g]);
                mma_tf32(o[n], a0, a1, a2, a3, b0, b1);
            }
        }
    }

    {
        const float inv0 = 1.0f / li0;
        const float inv1 = 1.0f / li1;
#pragma unroll
        for (int n = 0; n < 8; n++) {
            int col = h * HD + n * 8 + 2 * t;
            float2 v0 = make_float2(to_tf32(o[n][0] * inv0), to_tf32(o[n][1] * inv0));
            float2 v1 = make_float2(to_tf32(o[n][2] * inv1), to_tf32(o[n][3] * inv1));
            *(float2*)&ctx[((size_t)(b * SEQ + row0g)) * DOUT + col] = v0;
            *(float2*)&ctx[((size_t)(b * SEQ + row1g)) * DOUT + col] = v1;
        }
    }
}

// ----------------------------------------------------------------------------
// Launch.  Inputs: 0:x 1:mask 2:cos 3:sin 4:wq 5:wk 6:wv 7:wo 8:bo
// Launch order keeps the out-proj GEMM 6th so ncu (-s 5 -c 1) profiles it.
// ----------------------------------------------------------------------------
#define ATTN_SMEM_BYTES ((384 * QPAD) * 4)

extern "C" void kernel_launch(void* const* d_in, const int* in_sizes, int n_in,
                              void* d_out, int out_size)
{
    const float* x    = (const float*)d_in[0];
    const float* cosT = (const float*)d_in[2];
    const float* sinT = (const float*)d_in[3];
    const float* wq   = (const float*)d_in[4];
    const float* wk   = (const float*)d_in[5];
    const float* wv   = (const float*)d_in[6];
    const float* wo   = (const float*)d_in[7];
    const float* bo   = (const float*)d_in[8];
    float* out = (float*)d_out;

    float *q, *k, *v, *ctx, *xr, *wqT, *wkT, *wvT, *woT;
    cudaGetSymbolAddress((void**)&q,   g_q);
    cudaGetSymbolAddress((void**)&k,   g_k);
    cudaGetSymbolAddress((void**)&v,   g_v);
    cudaGetSymbolAddress((void**)&ctx, g_ctx);
    cudaGetSymbolAddress((void**)&xr,  g_xr);
    cudaGetSymbolAddress((void**)&wqT, g_wqT);
    cudaGetSymbolAddress((void**)&wkT, g_wkT);
    cudaGetSymbolAddress((void**)&wvT, g_wvT);
    cudaGetSymbolAddress((void**)&woT, g_woT);

    cudaFuncSetAttribute(gemm_blk_kernel,
                         cudaFuncAttributeMaxDynamicSharedMemorySize, GEMM_SMEM);
    cudaFuncSetAttribute(attn_tc_kernel,
                         cudaFuncAttributeMaxDynamicSharedMemorySize, ATTN_SMEM_BYTES);

    // 1-2: Prep (tf32-round x; transpose+round weights)
    prep_roundx<<<(MROWS * DIN / 4) / 256, 256>>>(x, xr);
    prep_transpose<<<10240, 256>>>(wq, wk, wv, wo, wqT, wkT, wvT, woT);

    // 3: Fused QKV projection (bulk-staged mma.sync)
    gemm_blk_kernel<<<dim3((DOUT + 2 * NKVD) / 128, MROWS / 128), 256, GEMM_SMEM>>>(
        xr, wqT, wkT, wvT, q, k, v, nullptr, 0);

    // 4: RoPE on q and k (single launch)
    rope_all_kernel<<<(80 * SEQ * 32) / 256, 256>>>(q, k, cosT, sinT);

    // 5: Tensor-core flash attention
    attn_tc_kernel<<<dim3(SEQ / 128, BATCH * NHEADS), 256, ATTN_SMEM_BYTES>>>(q, k, v, ctx);

    // 6: Output projection + bias (bulk-staged mma.sync) — profiled launch
    gemm_blk_kernel<<<dim3(DOUT / 128, MROWS / 128), 256, GEMM_SMEM>>>(
        ctx, woT, nullptr, nullptr, out, nullptr, nullptr, bo, 1);
}